// round 1
// baseline (speedup 1.0000x reference)
#include <cuda_runtime.h>
#include <math.h>

#define SEQ   8192
#define BATCH 2
#define EMB   512
#define NH    8
#define DH    64
#define NBLK  128      // SEQ / 64
#define BLK   64
#define MBL   8        // gathered blocks per query block
#define NGLOB 2
#define NWIN  3

// ---- device-global scratch (allocation-free) ----
__device__ float g_Q[(size_t)BATCH * NH * SEQ * DH];   // [b][h][s][d]
__device__ float g_K[(size_t)BATCH * NH * SEQ * DH];
__device__ float g_V[(size_t)BATCH * NH * SEQ * DH];
__device__ float g_AO[(size_t)BATCH * SEQ * EMB];      // [(b*S+s)][e]

// ============================================================
// QKV projection GEMM: C[b,h,s,d] = sum_e in[s,b,e]*W[h,e,d] + bias[h,d]
// Tiling: BM=128, BN=64(one head), BK=16; 256 thr, 8x4 microtile.
// ============================================================
__global__ __launch_bounds__(256, 4)
void proj_gemm(const float* __restrict__ A,   // (SEQ, BATCH, EMB)
               const float* __restrict__ W,   // (NH, EMB, DH)
               const float* __restrict__ bias,// (NH, DH)
               int mode)                      // 0=Q 1=K 2=V
{
    __shared__ float As[16][132];   // [k][m], padded
    __shared__ float Bs[16][68];    // [k][n], padded

    float* __restrict__ C = (mode == 0) ? g_Q : (mode == 1) ? g_K : g_V;

    const int tid = threadIdx.x;
    const int m0  = blockIdx.x * 128;
    const int h   = blockIdx.y;
    const int ty  = tid >> 4;        // 0..15 (m dir, 8 rows each)
    const int tx  = tid & 15;        // 0..15 (n dir, 4 cols each)

    float acc[8][4];
#pragma unroll
    for (int i = 0; i < 8; i++)
#pragma unroll
        for (int j = 0; j < 4; j++) acc[i][j] = 0.f;

    const int a_row = tid >> 2;          // 0..63
    const int a_c4  = (tid & 3) * 4;     // 0,4,8,12
    const int b_kl  = tid >> 4;          // 0..15
    const int b_nl  = (tid & 15) * 4;    // 0..60

    for (int k0 = 0; k0 < EMB; k0 += 16) {
        // A tile 128x16 (transposed into As[k][m])
#pragma unroll
        for (int i = 0; i < 2; i++) {
            int m = m0 + a_row + i * 64;
            int b = m >> 13;             // / SEQ
            int s = m & (SEQ - 1);
            float4 v = *(const float4*)&A[(size_t)(s * BATCH + b) * EMB + k0 + a_c4];
            As[a_c4 + 0][a_row + i * 64] = v.x;
            As[a_c4 + 1][a_row + i * 64] = v.y;
            As[a_c4 + 2][a_row + i * 64] = v.z;
            As[a_c4 + 3][a_row + i * 64] = v.w;
        }
        // B tile 16x64 (W[h, k0+kl, nl..nl+3])
        {
            float4 v = *(const float4*)&W[((size_t)h * EMB + (k0 + b_kl)) * DH + b_nl];
            Bs[b_kl][b_nl + 0] = v.x;
            Bs[b_kl][b_nl + 1] = v.y;
            Bs[b_kl][b_nl + 2] = v.z;
            Bs[b_kl][b_nl + 3] = v.w;
        }
        __syncthreads();

#pragma unroll
        for (int k = 0; k < 16; k++) {
            float a[8], bb[4];
            *(float4*)&a[0] = *(float4*)&As[k][ty * 8];
            *(float4*)&a[4] = *(float4*)&As[k][ty * 8 + 4];
            *(float4*)&bb[0] = *(float4*)&Bs[k][tx * 4];
#pragma unroll
            for (int i = 0; i < 8; i++)
#pragma unroll
                for (int j = 0; j < 4; j++)
                    acc[i][j] = fmaf(a[i], bb[j], acc[i][j]);
        }
        __syncthreads();
    }

    // epilogue: add bias, store to [b][h][s][d]
    float4 bv = *(const float4*)&bias[h * DH + tx * 4];
#pragma unroll
    for (int i = 0; i < 8; i++) {
        int m = m0 + ty * 8 + i;
        int b = m >> 13;
        int s = m & (SEQ - 1);
        float4 o;
        o.x = acc[i][0] + bv.x;
        o.y = acc[i][1] + bv.y;
        o.z = acc[i][2] + bv.z;
        o.w = acc[i][3] + bv.w;
        *(float4*)&C[(((size_t)b * NH + h) * SEQ + s) * DH + tx * 4] = o;
    }
}

// ============================================================
// Output projection: out[(s*B+b), n] = sum_e AO[(b*S+s), e] * out_w[n, e] + out_b[n]
// ============================================================
__global__ __launch_bounds__(256, 4)
void out_gemm(const float* __restrict__ Wo,   // (EMB, EMB) row-major [n][e]
              const float* __restrict__ bo,   // (EMB,)
              float* __restrict__ out)        // (SEQ, BATCH, EMB)
{
    __shared__ float As[16][132];
    __shared__ float Bs[16][68];

    const int tid = threadIdx.x;
    const int m0  = blockIdx.x * 128;
    const int n0  = blockIdx.y * 64;
    const int ty  = tid >> 4;
    const int tx  = tid & 15;

    float acc[8][4];
#pragma unroll
    for (int i = 0; i < 8; i++)
#pragma unroll
        for (int j = 0; j < 4; j++) acc[i][j] = 0.f;

    const int a_row = tid >> 2;
    const int a_c4  = (tid & 3) * 4;
    const int b_nl  = tid >> 2;          // 0..63
    const int b_kc  = (tid & 3) * 4;     // 0,4,8,12

    for (int k0 = 0; k0 < EMB; k0 += 16) {
#pragma unroll
        for (int i = 0; i < 2; i++) {
            int m = m0 + a_row + i * 64;
            float4 v = *(const float4*)&g_AO[(size_t)m * EMB + k0 + a_c4];
            As[a_c4 + 0][a_row + i * 64] = v.x;
            As[a_c4 + 1][a_row + i * 64] = v.y;
            As[a_c4 + 2][a_row + i * 64] = v.z;
            As[a_c4 + 3][a_row + i * 64] = v.w;
        }
        {
            float4 v = *(const float4*)&Wo[(size_t)(n0 + b_nl) * EMB + k0 + b_kc];
            Bs[b_kc + 0][b_nl] = v.x;
            Bs[b_kc + 1][b_nl] = v.y;
            Bs[b_kc + 2][b_nl] = v.z;
            Bs[b_kc + 3][b_nl] = v.w;
        }
        __syncthreads();

#pragma unroll
        for (int k = 0; k < 16; k++) {
            float a[8], bb[4];
            *(float4*)&a[0] = *(float4*)&As[k][ty * 8];
            *(float4*)&a[4] = *(float4*)&As[k][ty * 8 + 4];
            *(float4*)&bb[0] = *(float4*)&Bs[k][tx * 4];
#pragma unroll
            for (int i = 0; i < 8; i++)
#pragma unroll
                for (int j = 0; j < 4; j++)
                    acc[i][j] = fmaf(a[i], bb[j], acc[i][j]);
        }
        __syncthreads();
    }

    float4 bv = *(const float4*)&bo[n0 + tx * 4];
#pragma unroll
    for (int i = 0; i < 8; i++) {
        int m = m0 + ty * 8 + i;
        int b = m >> 13;
        int s = m & (SEQ - 1);
        float4 o;
        o.x = acc[i][0] + bv.x;
        o.y = acc[i][1] + bv.y;
        o.z = acc[i][2] + bv.z;
        o.w = acc[i][3] + bv.w;
        *(float4*)&out[(size_t)(s * BATCH + b) * EMB + n0 + tx * 4] = o;
    }
}

// ============================================================
// Block-sparse attention with online softmax.
// Grid: (NBLK, BATCH*NH). 256 threads: (r = tid/4 in 0..63, g = tid&3).
// Thread (r,g) owns output dims [16g, 16g+16) of q-row r.
// ============================================================
#define QS_STRIDE 68
#define PS_STRIDE 65
#define SMEM_FLOATS (3 * 64 * QS_STRIDE + 64 * PS_STRIDE)

__global__ __launch_bounds__(256)
void sparse_attn(const int* __restrict__ rand_idx)
{
    extern __shared__ float sm[];
    float* Qs = sm;
    float* Ks = Qs + 64 * QS_STRIDE;
    float* Vs = Ks + 64 * QS_STRIDE;
    float* Ps = Vs + 64 * QS_STRIDE;

    const int nb  = blockIdx.x;
    const int bh  = blockIdx.y;               // b*NH + h
    const int tid = threadIdx.x;
    const int r   = tid >> 2;
    const int g   = tid & 3;
    const size_t base = (size_t)bh * SEQ * DH;

    // load Q block (64x64) into smem
#pragma unroll
    for (int i = 0; i < 4; i++) {
        int idx = tid + 256 * i;              // float4 index, 0..1023
        int row = idx >> 4;
        int c4  = (idx & 15) * 4;
        *(float4*)&Qs[row * QS_STRIDE + c4] =
            *(const float4*)&g_Q[base + (size_t)(nb * BLK + row) * DH + c4];
    }

    float o[16];
#pragma unroll
    for (int i = 0; i < 16; i++) o[i] = 0.f;
    float mrow = -1e30f, lrow = 0.f;
    const float CC = 0.18033688011112042f;    // (1/sqrt(64)) * log2(e)

    for (int j = 0; j < MBL; j++) {
        int kb;
        if (j < NGLOB)            kb = j;
        else if (j < NGLOB + NWIN) kb = (nb + (j - NGLOB) - 1 + NBLK) & (NBLK - 1);
        else                      kb = rand_idx[nb * 3 + (j - (NGLOB + NWIN))];

        __syncthreads();   // previous iter done with Ks/Vs/Ps
#pragma unroll
        for (int i = 0; i < 4; i++) {
            int idx = tid + 256 * i;
            int row = idx >> 4;
            int c4  = (idx & 15) * 4;
            size_t ga = base + (size_t)(kb * BLK + row) * DH + c4;
            *(float4*)&Ks[row * QS_STRIDE + c4] = *(const float4*)&g_K[ga];
            *(float4*)&Vs[row * QS_STRIDE + c4] = *(const float4*)&g_V[ga];
        }
        __syncthreads();

        // scores: p[ki] = dot(Q[r], K[4*ki + g]) over 64 dims
        float p[16];
#pragma unroll
        for (int ki = 0; ki < 16; ki++) p[ki] = 0.f;
#pragma unroll 4
        for (int dc = 0; dc < 16; dc++) {
            float4 qv = *(float4*)&Qs[r * QS_STRIDE + dc * 4];
#pragma unroll
            for (int ki = 0; ki < 16; ki++) {
                float4 kv = *(float4*)&Ks[(4 * ki + g) * QS_STRIDE + dc * 4];
                p[ki] = fmaf(qv.x, kv.x, p[ki]);
                p[ki] = fmaf(qv.y, kv.y, p[ki]);
                p[ki] = fmaf(qv.z, kv.z, p[ki]);
                p[ki] = fmaf(qv.w, kv.w, p[ki]);
            }
        }

        // online softmax (row state shared across the 4 lanes of a row)
        float mloc = p[0];
#pragma unroll
        for (int ki = 1; ki < 16; ki++) mloc = fmaxf(mloc, p[ki]);
        mloc = fmaxf(mloc, __shfl_xor_sync(0xffffffffu, mloc, 1));
        mloc = fmaxf(mloc, __shfl_xor_sync(0xffffffffu, mloc, 2));
        float mnew  = fmaxf(mrow, mloc);
        float alpha = exp2f((mrow - mnew) * CC);
        float ls = 0.f;
#pragma unroll
        for (int ki = 0; ki < 16; ki++) {
            p[ki] = exp2f((p[ki] - mnew) * CC);
            ls += p[ki];
            Ps[r * PS_STRIDE + 4 * ki + g] = p[ki];
        }
        ls += __shfl_xor_sync(0xffffffffu, ls, 1);
        ls += __shfl_xor_sync(0xffffffffu, ls, 2);
        lrow = lrow * alpha + ls;
        mrow = mnew;
#pragma unroll
        for (int i = 0; i < 16; i++) o[i] *= alpha;
        __syncwarp();

        // PV: o[16g..16g+16) += sum_k P[r][k] * V[k][d]
#pragma unroll 8
        for (int k = 0; k < 64; k++) {
            float pv = Ps[r * PS_STRIDE + k];
            const float* vrow = &Vs[k * QS_STRIDE + g * 16];
            float4 v0 = *(const float4*)&vrow[0];
            float4 v1 = *(const float4*)&vrow[4];
            float4 v2 = *(const float4*)&vrow[8];
            float4 v3 = *(const float4*)&vrow[12];
            o[0]  = fmaf(pv, v0.x, o[0]);  o[1]  = fmaf(pv, v0.y, o[1]);
            o[2]  = fmaf(pv, v0.z, o[2]);  o[3]  = fmaf(pv, v0.w, o[3]);
            o[4]  = fmaf(pv, v1.x, o[4]);  o[5]  = fmaf(pv, v1.y, o[5]);
            o[6]  = fmaf(pv, v1.z, o[6]);  o[7]  = fmaf(pv, v1.w, o[7]);
            o[8]  = fmaf(pv, v2.x, o[8]);  o[9]  = fmaf(pv, v2.y, o[9]);
            o[10] = fmaf(pv, v2.z, o[10]); o[11] = fmaf(pv, v2.w, o[11]);
            o[12] = fmaf(pv, v3.x, o[12]); o[13] = fmaf(pv, v3.y, o[13]);
            o[14] = fmaf(pv, v3.z, o[14]); o[15] = fmaf(pv, v3.w, o[15]);
        }
    }

    // finalize and store to AO[(b*S+s)][h*64 + 16g ..]
    const int b = bh >> 3, h = bh & 7;
    float inv = 1.f / lrow;
    int s = nb * BLK + r;
    size_t ob = (size_t)(b * SEQ + s) * EMB + h * DH + g * 16;
#pragma unroll
    for (int c = 0; c < 4; c++) {
        float4 ov;
        ov.x = o[4 * c + 0] * inv;
        ov.y = o[4 * c + 1] * inv;
        ov.z = o[4 * c + 2] * inv;
        ov.w = o[4 * c + 3] * inv;
        *(float4*)&g_AO[ob + 4 * c] = ov;
    }
}

// ============================================================
extern "C" void kernel_launch(void* const* d_in, const int* in_sizes, int n_in,
                              void* d_out, int out_size)
{
    const float* query   = (const float*)d_in[0];
    const float* key_inp = (const float*)d_in[1];
    const float* value   = (const float*)d_in[2];
    const float* q_w     = (const float*)d_in[3];
    const float* k_w     = (const float*)d_in[4];
    const float* v_w     = (const float*)d_in[5];
    const float* q_b     = (const float*)d_in[6];
    const float* k_b     = (const float*)d_in[7];
    const float* v_b     = (const float*)d_in[8];
    const float* out_w   = (const float*)d_in[9];
    const float* out_b   = (const float*)d_in[10];
    const int*   rand_idx= (const int*)d_in[11];
    float* out = (float*)d_out;

    static bool attr_set = false;
    if (!attr_set) {
        cudaFuncSetAttribute(sparse_attn,
                             cudaFuncAttributeMaxDynamicSharedMemorySize,
                             SMEM_FLOATS * (int)sizeof(float));
        attr_set = true;
    }

    dim3 gProj(SEQ * BATCH / 128, NH);
    proj_gemm<<<gProj, 256>>>(query,   q_w, q_b, 0);
    proj_gemm<<<gProj, 256>>>(key_inp, k_w, k_b, 1);
    proj_gemm<<<gProj, 256>>>(value,   v_w, v_b, 2);

    dim3 gAttn(NBLK, BATCH * NH);
    sparse_attn<<<gAttn, 256, SMEM_FLOATS * (int)sizeof(float)>>>(rand_idx);

    dim3 gOut(SEQ * BATCH / 128, EMB / 64);
    out_gemm<<<gOut, 256>>>(out_w, out_b, out);
}

// round 2
// speedup vs baseline: 1.7594x; 1.7594x over previous
#include <cuda_runtime.h>
#include <math.h>

#define SEQ   8192
#define BATCH 2
#define EMB   512
#define NH    8
#define DH    64
#define NBLK  128      // SEQ / 64
#define BLK   64
#define MBL   8        // gathered blocks per query block
#define NGLOB 2
#define NWIN  3

// ---- device-global scratch (allocation-free) ----
__device__ float g_Q[(size_t)BATCH * NH * SEQ * DH];   // [b][h][s][d]
__device__ float g_K[(size_t)BATCH * NH * SEQ * DH];
__device__ float g_V[(size_t)BATCH * NH * SEQ * DH];
__device__ float g_AO[(size_t)BATCH * SEQ * EMB];      // [(b*S+s)][e]

// ============================================================
// QKV projection GEMM: C[b,h,s,d] = sum_e in[s,b,e]*W[h,e,d] + bias[h,d]
// ============================================================
__global__ __launch_bounds__(256, 4)
void proj_gemm(const float* __restrict__ A,   // (SEQ, BATCH, EMB)
               const float* __restrict__ W,   // (NH, EMB, DH)
               const float* __restrict__ bias,// (NH, DH)
               int mode)                      // 0=Q 1=K 2=V
{
    __shared__ float As[16][132];   // [k][m], padded
    __shared__ float Bs[16][68];    // [k][n], padded

    float* __restrict__ C = (mode == 0) ? g_Q : (mode == 1) ? g_K : g_V;

    const int tid = threadIdx.x;
    const int m0  = blockIdx.x * 128;
    const int h   = blockIdx.y;
    const int ty  = tid >> 4;        // 0..15 (m dir, 8 rows each)
    const int tx  = tid & 15;        // 0..15 (n dir, 4 cols each)

    float acc[8][4];
#pragma unroll
    for (int i = 0; i < 8; i++)
#pragma unroll
        for (int j = 0; j < 4; j++) acc[i][j] = 0.f;

    const int a_row = tid >> 2;          // 0..63
    const int a_c4  = (tid & 3) * 4;     // 0,4,8,12
    const int b_kl  = tid >> 4;          // 0..15
    const int b_nl  = (tid & 15) * 4;    // 0..60

    for (int k0 = 0; k0 < EMB; k0 += 16) {
#pragma unroll
        for (int i = 0; i < 2; i++) {
            int m = m0 + a_row + i * 64;
            int b = m >> 13;             // / SEQ
            int s = m & (SEQ - 1);
            float4 v = *(const float4*)&A[(size_t)(s * BATCH + b) * EMB + k0 + a_c4];
            As[a_c4 + 0][a_row + i * 64] = v.x;
            As[a_c4 + 1][a_row + i * 64] = v.y;
            As[a_c4 + 2][a_row + i * 64] = v.z;
            As[a_c4 + 3][a_row + i * 64] = v.w;
        }
        {
            float4 v = *(const float4*)&W[((size_t)h * EMB + (k0 + b_kl)) * DH + b_nl];
            Bs[b_kl][b_nl + 0] = v.x;
            Bs[b_kl][b_nl + 1] = v.y;
            Bs[b_kl][b_nl + 2] = v.z;
            Bs[b_kl][b_nl + 3] = v.w;
        }
        __syncthreads();

#pragma unroll
        for (int k = 0; k < 16; k++) {
            float a[8], bb[4];
            *(float4*)&a[0] = *(float4*)&As[k][ty * 8];
            *(float4*)&a[4] = *(float4*)&As[k][ty * 8 + 4];
            *(float4*)&bb[0] = *(float4*)&Bs[k][tx * 4];
#pragma unroll
            for (int i = 0; i < 8; i++)
#pragma unroll
                for (int j = 0; j < 4; j++)
                    acc[i][j] = fmaf(a[i], bb[j], acc[i][j]);
        }
        __syncthreads();
    }

    float4 bv = *(const float4*)&bias[h * DH + tx * 4];
#pragma unroll
    for (int i = 0; i < 8; i++) {
        int m = m0 + ty * 8 + i;
        int b = m >> 13;
        int s = m & (SEQ - 1);
        float4 o;
        o.x = acc[i][0] + bv.x;
        o.y = acc[i][1] + bv.y;
        o.z = acc[i][2] + bv.z;
        o.w = acc[i][3] + bv.w;
        *(float4*)&C[(((size_t)b * NH + h) * SEQ + s) * DH + tx * 4] = o;
    }
}

// ============================================================
// Output projection: out[(s*B+b), n] = sum_e AO[(b*S+s), e] * out_w[n, e] + out_b[n]
// ============================================================
__global__ __launch_bounds__(256, 4)
void out_gemm(const float* __restrict__ Wo,   // (EMB, EMB) row-major [n][e]
              const float* __restrict__ bo,   // (EMB,)
              float* __restrict__ out)        // (SEQ, BATCH, EMB)
{
    __shared__ float As[16][132];
    __shared__ float Bs[16][68];

    const int tid = threadIdx.x;
    const int m0  = blockIdx.x * 128;
    const int n0  = blockIdx.y * 64;
    const int ty  = tid >> 4;
    const int tx  = tid & 15;

    float acc[8][4];
#pragma unroll
    for (int i = 0; i < 8; i++)
#pragma unroll
        for (int j = 0; j < 4; j++) acc[i][j] = 0.f;

    const int a_row = tid >> 2;
    const int a_c4  = (tid & 3) * 4;
    const int b_nl  = tid >> 2;          // 0..63
    const int b_kc  = (tid & 3) * 4;     // 0,4,8,12

    for (int k0 = 0; k0 < EMB; k0 += 16) {
#pragma unroll
        for (int i = 0; i < 2; i++) {
            int m = m0 + a_row + i * 64;
            float4 v = *(const float4*)&g_AO[(size_t)m * EMB + k0 + a_c4];
            As[a_c4 + 0][a_row + i * 64] = v.x;
            As[a_c4 + 1][a_row + i * 64] = v.y;
            As[a_c4 + 2][a_row + i * 64] = v.z;
            As[a_c4 + 3][a_row + i * 64] = v.w;
        }
        {
            float4 v = *(const float4*)&Wo[(size_t)(n0 + b_nl) * EMB + k0 + b_kc];
            Bs[b_kc + 0][b_nl] = v.x;
            Bs[b_kc + 1][b_nl] = v.y;
            Bs[b_kc + 2][b_nl] = v.z;
            Bs[b_kc + 3][b_nl] = v.w;
        }
        __syncthreads();

#pragma unroll
        for (int k = 0; k < 16; k++) {
            float a[8], bb[4];
            *(float4*)&a[0] = *(float4*)&As[k][ty * 8];
            *(float4*)&a[4] = *(float4*)&As[k][ty * 8 + 4];
            *(float4*)&bb[0] = *(float4*)&Bs[k][tx * 4];
#pragma unroll
            for (int i = 0; i < 8; i++)
#pragma unroll
                for (int j = 0; j < 4; j++)
                    acc[i][j] = fmaf(a[i], bb[j], acc[i][j]);
        }
        __syncthreads();
    }

    float4 bv = *(const float4*)&bo[n0 + tx * 4];
#pragma unroll
    for (int i = 0; i < 8; i++) {
        int m = m0 + ty * 8 + i;
        int b = m >> 13;
        int s = m & (SEQ - 1);
        float4 o;
        o.x = acc[i][0] + bv.x;
        o.y = acc[i][1] + bv.y;
        o.z = acc[i][2] + bv.z;
        o.w = acc[i][3] + bv.w;
        *(float4*)&out[(size_t)(s * BATCH + b) * EMB + n0 + tx * 4] = o;
    }
}

// ============================================================
// Block-sparse attention v2: GEMM-style register tiling.
// Grid (NBLK, BATCH*NH), 256 threads.
// Per iteration: 2 key-blocks (64 q-rows x 128 keys).
// QK layout: warp ty=tid>>5 owns rows ty*8..+7; lane owns keys lane*4..+3.
// PV layout: my=tid>>4 owns rows my*4..+3; nx=tid&15 owns dims nx*4..+3.
// Qt/Kt stored transposed (d-major) with XOR swizzle; Pt transposed; Pt aliases Kt.
// ============================================================
#define QT_OFF   0
#define KT_OFF   4096                 // Qt = 64*64
#define VS_OFF   (KT_OFF + 8704)     // union(Kt 64*128, Pt 128*68)
#define AL_OFF   (VS_OFF + 128*68)
#define LL_OFF   (AL_OFF + 64)
#define SA_FLOATS (LL_OFF + 64)

__global__ __launch_bounds__(256, 2)
void sparse_attn(const int* __restrict__ rand_idx)
{
    extern __shared__ float sm[];
    float* Qt = sm + QT_OFF;          // [d][64 rows], swizzled, stride 64
    float* Kt = sm + KT_OFF;          // [d][128 keys], swizzled, stride 128
    float* Pt = sm + KT_OFF;          // [128 keys][68 rows] (aliases Kt)
    float* Vs = sm + VS_OFF;          // [128 keys][68 dims]
    float* alpha_s = sm + AL_OFF;     // [64]
    float* l_s     = sm + LL_OFF;     // [64]

    const int nb  = blockIdx.x;
    const int bh  = blockIdx.y;
    const int tid = threadIdx.x;
    const int ty   = tid >> 5;        // warp id 0..7
    const int lane = tid & 31;
    const int my   = tid >> 4;        // 0..15
    const int nx   = tid & 15;
    const size_t base = (size_t)bh * SEQ * DH;
    const float CC = 0.18033688011112042f;   // (1/sqrt(64)) * log2(e)

    // ---- stage Q transposed + swizzled ----
#pragma unroll
    for (int i = 0; i < 4; i++) {
        int idx = tid + 256 * i;              // 0..1023
        int row = idx >> 4;
        int c4  = (idx & 15) * 4;
        int c   = c4 >> 2;
        float4 q = *(const float4*)&g_Q[base + (size_t)(nb * BLK + row) * DH + c4];
        int pc = (((row >> 2) ^ c) << 2) + (row & 3);
        Qt[((c4 + 0) << 6) + pc] = q.x;
        Qt[((c4 + 1) << 6) + pc] = q.y;
        Qt[((c4 + 2) << 6) + pc] = q.z;
        Qt[((c4 + 3) << 6) + pc] = q.w;
    }

    float o[4][4];
#pragma unroll
    for (int i = 0; i < 4; i++)
#pragma unroll
        for (int j = 0; j < 4; j++) o[i][j] = 0.f;
    float mst[8], lst[8];
#pragma unroll
    for (int i = 0; i < 8; i++) { mst[i] = -1e30f; lst[i] = 0.f; }

    for (int jj = 0; jj < 4; jj++) {
        // key-block indices for this pair
        int kbs[2];
#pragma unroll
        for (int t = 0; t < 2; t++) {
            int j = 2 * jj + t;
            int kb;
            if (j < NGLOB)             kb = j;
            else if (j < NGLOB + NWIN) kb = (nb + (j - NGLOB) - 1 + NBLK) & (NBLK - 1);
            else                       kb = rand_idx[nb * 3 + (j - (NGLOB + NWIN))];
            kbs[t] = kb;
        }

        __syncthreads();   // prev iter done reading Pt(Kt)/Vs/alpha

        // ---- stage K (transposed+swizzled) and V (row-major, stride 68) ----
#pragma unroll
        for (int i = 0; i < 8; i++) {
            int idx = tid + 256 * i;          // 0..2047
            int key = idx >> 4;               // 0..127
            int c4  = (idx & 15) * 4;
            int c   = c4 >> 2;
            int kb  = (key < 64) ? kbs[0] : kbs[1];
            size_t ga = base + (size_t)(kb * BLK + (key & 63)) * DH + c4;
            float4 kv = *(const float4*)&g_K[ga];
            float4 vv = *(const float4*)&g_V[ga];
            int pc = (((key >> 2) ^ c) << 2) + (key & 3);
            Kt[((c4 + 0) << 7) + pc] = kv.x;
            Kt[((c4 + 1) << 7) + pc] = kv.y;
            Kt[((c4 + 2) << 7) + pc] = kv.z;
            Kt[((c4 + 3) << 7) + pc] = kv.w;
            *(float4*)&Vs[key * 68 + c4] = vv;
        }
        __syncthreads();

        // ---- QK: s[8 rows][4 keys] ----
        float s[8][4];
#pragma unroll
        for (int i = 0; i < 8; i++)
#pragma unroll
            for (int j = 0; j < 4; j++) s[i][j] = 0.f;

#pragma unroll 8
        for (int d = 0; d < 64; d++) {
            int sw = (d >> 2) & 15;
            float4 q0 = *(float4*)&Qt[(d << 6) + (((2 * ty)     ^ sw) << 2)];
            float4 q1 = *(float4*)&Qt[(d << 6) + (((2 * ty + 1) ^ sw) << 2)];
            float4 kk = *(float4*)&Kt[(d << 7) + ((lane ^ sw) << 2)];
            float qa[8] = {q0.x, q0.y, q0.z, q0.w, q1.x, q1.y, q1.z, q1.w};
            float kb4[4] = {kk.x, kk.y, kk.z, kk.w};
#pragma unroll
            for (int i = 0; i < 8; i++)
#pragma unroll
                for (int j = 0; j < 4; j++)
                    s[i][j] = fmaf(qa[i], kb4[j], s[i][j]);
        }

        // ---- online softmax (warp-wide: each warp owns its 8 rows) ----
        float alpha[8];
#pragma unroll
        for (int i = 0; i < 8; i++) {
            float mx = fmaxf(fmaxf(s[i][0], s[i][1]), fmaxf(s[i][2], s[i][3]));
#pragma unroll
            for (int off = 16; off > 0; off >>= 1)
                mx = fmaxf(mx, __shfl_xor_sync(0xffffffffu, mx, off));
            float mnew = fmaxf(mst[i], mx);
            alpha[i] = exp2f((mst[i] - mnew) * CC);
            float ls = 0.f;
#pragma unroll
            for (int j = 0; j < 4; j++) {
                s[i][j] = exp2f((s[i][j] - mnew) * CC);
                ls += s[i][j];
            }
#pragma unroll
            for (int off = 16; off > 0; off >>= 1)
                ls += __shfl_xor_sync(0xffffffffu, ls, off);
            lst[i] = lst[i] * alpha[i] + ls;
            mst[i] = mnew;
        }

        __syncthreads();   // all warps done reading Kt; Pt may overwrite it

        // write row stats (replicated in warp; lane i<8 writes row ty*8+i)
#pragma unroll
        for (int i = 0; i < 8; i++) {
            if (lane == i) {
                alpha_s[8 * ty + i] = alpha[i];
                l_s[8 * ty + i]     = lst[i];
            }
        }
        // write Pt[key][row] (transposed, stride 68)
#pragma unroll
        for (int j = 0; j < 4; j++) {
            float4 a = make_float4(s[0][j], s[1][j], s[2][j], s[3][j]);
            float4 b = make_float4(s[4][j], s[5][j], s[6][j], s[7][j]);
            *(float4*)&Pt[(4 * lane + j) * 68 + 8 * ty]     = a;
            *(float4*)&Pt[(4 * lane + j) * 68 + 8 * ty + 4] = b;
        }
        __syncthreads();

        // ---- PV: O[4 rows][4 dims] over 128 keys ----
        float ar[4];
#pragma unroll
        for (int i = 0; i < 4; i++) ar[i] = alpha_s[4 * my + i];
#pragma unroll
        for (int i = 0; i < 4; i++)
#pragma unroll
            for (int j = 0; j < 4; j++) o[i][j] *= ar[i];

#pragma unroll 4
        for (int k = 0; k < 128; k++) {
            float4 p = *(float4*)&Pt[k * 68 + 4 * my];
            float4 v = *(float4*)&Vs[k * 68 + 4 * nx];
            float pa[4] = {p.x, p.y, p.z, p.w};
            float va[4] = {v.x, v.y, v.z, v.w};
#pragma unroll
            for (int i = 0; i < 4; i++)
#pragma unroll
                for (int j = 0; j < 4; j++)
                    o[i][j] = fmaf(pa[i], va[j], o[i][j]);
        }
    }

    // ---- finalize (l_s valid: written before last PV sync) ----
    const int b = bh >> 3, h = bh & 7;
#pragma unroll
    for (int i = 0; i < 4; i++) {
        float inv = 1.f / l_s[4 * my + i];
        int srow = nb * BLK + 4 * my + i;
        float4 ov;
        ov.x = o[i][0] * inv;
        ov.y = o[i][1] * inv;
        ov.z = o[i][2] * inv;
        ov.w = o[i][3] * inv;
        *(float4*)&g_AO[(size_t)(b * SEQ + srow) * EMB + h * DH + 4 * nx] = ov;
    }
}

// ============================================================
extern "C" void kernel_launch(void* const* d_in, const int* in_sizes, int n_in,
                              void* d_out, int out_size)
{
    const float* query   = (const float*)d_in[0];
    const float* key_inp = (const float*)d_in[1];
    const float* value   = (const float*)d_in[2];
    const float* q_w     = (const float*)d_in[3];
    const float* k_w     = (const float*)d_in[4];
    const float* v_w     = (const float*)d_in[5];
    const float* q_b     = (const float*)d_in[6];
    const float* k_b     = (const float*)d_in[7];
    const float* v_b     = (const float*)d_in[8];
    const float* out_w   = (const float*)d_in[9];
    const float* out_b   = (const float*)d_in[10];
    const int*   rand_idx= (const int*)d_in[11];
    float* out = (float*)d_out;

    static bool attr_set = false;
    if (!attr_set) {
        cudaFuncSetAttribute(sparse_attn,
                             cudaFuncAttributeMaxDynamicSharedMemorySize,
                             SA_FLOATS * (int)sizeof(float));
        attr_set = true;
    }

    dim3 gProj(SEQ * BATCH / 128, NH);
    proj_gemm<<<gProj, 256>>>(query,   q_w, q_b, 0);
    proj_gemm<<<gProj, 256>>>(key_inp, k_w, k_b, 1);
    proj_gemm<<<gProj, 256>>>(value,   v_w, v_b, 2);

    dim3 gAttn(NBLK, BATCH * NH);
    sparse_attn<<<gAttn, 256, SA_FLOATS * (int)sizeof(float)>>>(rand_idx);

    dim3 gOut(SEQ * BATCH / 128, EMB / 64);
    out_gemm<<<gOut, 256>>>(out_w, out_b, out);
}

// round 4
// speedup vs baseline: 2.2767x; 1.2940x over previous
#include <cuda_runtime.h>
#include <cuda_bf16.h>
#include <math.h>
#include <cstdint>

#define SEQ   8192
#define BATCH 2
#define EMB   512
#define NH    8
#define DH    64
#define NBLK  128      // SEQ / 64
#define BLK   64
#define MBL   8        // gathered blocks per query block
#define NGLOB 2
#define NWIN  3

// ---- device-global scratch (allocation-free) ----
__device__ float g_Q[(size_t)BATCH * NH * SEQ * DH];   // [b][h][s][d]
__device__ float g_K[(size_t)BATCH * NH * SEQ * DH];
__device__ float g_V[(size_t)BATCH * NH * SEQ * DH];
__device__ float g_AO[(size_t)BATCH * SEQ * EMB];      // [(b*S+s)][e]
// bf16 hi/lo split weights: [mat][n][k], mat: 0=q 1=k 2=v 3=out
__device__ __nv_bfloat16 g_Whi[4u * 512u * 512u];
__device__ __nv_bfloat16 g_Wlo[4u * 512u * 512u];

// ============================================================
// helpers (baseline PTX only — no 'a'-suffix features)
// ============================================================
__device__ __forceinline__ uint32_t smem_u32(const void* p) {
    uint32_t a;
    asm("{ .reg .u64 t; cvta.to.shared.u64 t, %1; cvt.u32.u64 %0, t; }"
        : "=r"(a) : "l"(p));
    return a;
}
__device__ __forceinline__ void ldm_x4(uint32_t* r, uint32_t addr) {
    asm volatile("ldmatrix.sync.aligned.m8n8.x4.shared.b16 {%0,%1,%2,%3}, [%4];"
                 : "=r"(r[0]), "=r"(r[1]), "=r"(r[2]), "=r"(r[3]) : "r"(addr));
}
__device__ __forceinline__ void mma_bf16(float* d, const uint32_t* a, const uint32_t* b) {
    asm volatile(
        "mma.sync.aligned.m16n8k16.row.col.f32.bf16.bf16.f32 "
        "{%0,%1,%2,%3}, {%4,%5,%6,%7}, {%8,%9}, {%0,%1,%2,%3};"
        : "+f"(d[0]), "+f"(d[1]), "+f"(d[2]), "+f"(d[3])
        : "r"(a[0]), "r"(a[1]), "r"(a[2]), "r"(a[3]), "r"(b[0]), "r"(b[1]));
}

// ============================================================
// Weight conversion: fp32 -> bf16 hi/lo, layout [mat][n][k]
// proj weights (NH,EMB,DH): n = h*64+d, k = e. out_w (EMB,EMB): n,k direct.
// ============================================================
__global__ void conv_weights(const float* __restrict__ qw, const float* __restrict__ kw,
                             const float* __restrict__ vw, const float* __restrict__ ow)
{
    const int mat = blockIdx.y;
    const int n   = blockIdx.x;
    const float* src = (mat == 0) ? qw : (mat == 1) ? kw : (mat == 2) ? vw : ow;
    for (int k = threadIdx.x; k < 512; k += 256) {
        float v;
        if (mat < 3) v = src[((size_t)(n >> 6) * 512 + k) * 64 + (n & 63)];
        else         v = src[(size_t)n * 512 + k];
        __nv_bfloat16 h = __float2bfloat16(v);
        __nv_bfloat16 l = __float2bfloat16(v - __bfloat162float(h));
        size_t o = (size_t)mat * 262144 + (size_t)n * 512 + k;
        g_Whi[o] = h;
        g_Wlo[o] = l;
    }
}

// ============================================================
// HMMA GEMM (mma.sync bf16, fp32-accurate via hi/lo 3-term split)
// C[16384 x 512] = A[16384 x 512] * W^T   (W stored [n][k])
// Grid (128, 4): CTA tile 128(M) x 128(N), BK=32, 16 K-iters.
// 8 warps: wm = wid>>2 (2 in M), wn = wid&3 (4 in N); warp tile 64x32.
// Smem rows 64B, swizzle seg ^= (row>>1)&3 -> conflict-free ldmatrix.
// ============================================================
__global__ __launch_bounds__(256)
void gemm_mma(const float* __restrict__ Ain, const float* __restrict__ bias,
              float* __restrict__ Cout, int mode)
{
    __shared__ __nv_bfloat16 sAhi[128 * 32];
    __shared__ __nv_bfloat16 sAlo[128 * 32];
    __shared__ __nv_bfloat16 sBhi[128 * 32];
    __shared__ __nv_bfloat16 sBlo[128 * 32];

    const int tid  = threadIdx.x;
    const int wid  = tid >> 5;
    const int lane = tid & 31;
    const int wm   = wid >> 2;
    const int wn   = wid & 3;
    const int m0   = blockIdx.x * 128;
    const int n0   = blockIdx.y * 128;

    const float* __restrict__ A = (mode == 3) ? g_AO : Ain;
    const __nv_bfloat16* __restrict__ Bh = g_Whi + (size_t)mode * 262144;
    const __nv_bfloat16* __restrict__ Bl = g_Wlo + (size_t)mode * 262144;

    const uint32_t aAhi = smem_u32(sAhi);
    const uint32_t aAlo = smem_u32(sAlo);
    const uint32_t aBhi = smem_u32(sBhi);
    const uint32_t aBlo = smem_u32(sBlo);

    float acc[4][4][4];
#pragma unroll
    for (int i = 0; i < 4; i++)
#pragma unroll
        for (int j = 0; j < 4; j++)
#pragma unroll
            for (int r = 0; r < 4; r++) acc[i][j][r] = 0.f;

    const int tile = lane >> 3;          // 0..3
    const int r8   = lane & 7;

    for (int k0 = 0; k0 < 512; k0 += 32) {
        __syncthreads();
        // ---- stage A (128x32 fp32 -> hi/lo bf16, swizzled) ----
#pragma unroll
        for (int i = 0; i < 4; i++) {
            int idx = tid + 256 * i;              // 0..1023 float4s
            int row = idx >> 3;
            int c4  = (idx & 7) * 4;
            float4 v = *(const float4*)&A[(size_t)(m0 + row) * 512 + k0 + c4];
            __nv_bfloat16 h0 = __float2bfloat16(v.x);
            __nv_bfloat16 h1 = __float2bfloat16(v.y);
            __nv_bfloat16 h2 = __float2bfloat16(v.z);
            __nv_bfloat16 h3 = __float2bfloat16(v.w);
            __nv_bfloat16 l0 = __float2bfloat16(v.x - __bfloat162float(h0));
            __nv_bfloat16 l1 = __float2bfloat16(v.y - __bfloat162float(h1));
            __nv_bfloat16 l2 = __float2bfloat16(v.z - __bfloat162float(h2));
            __nv_bfloat16 l3 = __float2bfloat16(v.w - __bfloat162float(h3));
            int seg = c4 >> 3;
            int wi  = (c4 & 4) << 1;              // 0 or 8 bytes
            uint32_t off = (uint32_t)(row * 64 + ((seg ^ ((row >> 1) & 3)) << 4) + wi);
            *(__nv_bfloat162*)((char*)sAhi + off)     = __halves2bfloat162(h0, h1);
            *(__nv_bfloat162*)((char*)sAhi + off + 4) = __halves2bfloat162(h2, h3);
            *(__nv_bfloat162*)((char*)sAlo + off)     = __halves2bfloat162(l0, l1);
            *(__nv_bfloat162*)((char*)sAlo + off + 4) = __halves2bfloat162(l2, l3);
        }
        // ---- stage B hi/lo (128 rows x 32 bf16, swizzled) ----
#pragma unroll
        for (int i = 0; i < 2; i++) {
            int idx = tid + 256 * i;              // 0..511 16B-segs
            int row = idx >> 2;
            int seg = idx & 3;
            uint32_t off = (uint32_t)(row * 64 + ((seg ^ ((row >> 1) & 3)) << 4));
            *(float4*)((char*)sBhi + off) = *(const float4*)&Bh[(size_t)(n0 + row) * 512 + k0 + seg * 8];
            *(float4*)((char*)sBlo + off) = *(const float4*)&Bl[(size_t)(n0 + row) * 512 + k0 + seg * 8];
        }
        __syncthreads();

#pragma unroll
        for (int ks = 0; ks < 2; ks++) {
            const int k16 = ks * 16;
            // A fragment addrs: tiles (m,k),(m+8,k),(m,k+8),(m+8,k+8)
            const int arow_off = r8 + ((tile & 1) << 3);
            const int akc  = k16 + ((tile >= 2) ? 8 : 0);
            const int aseg = akc >> 3;
            // B fragment addrs (x4 covers 2 n-frags):
            const int brow_off = r8 + ((tile >> 1) << 3);
            const int bkc  = k16 + ((tile & 1) ? 8 : 0);
            const int bseg = bkc >> 3;

            uint32_t ah[4][4], bhf[2][4];
#pragma unroll
            for (int mi = 0; mi < 4; mi++) {
                int row = wm * 64 + mi * 16 + arow_off;
                ldm_x4(ah[mi], aAhi + (uint32_t)(row * 64 + ((aseg ^ ((row >> 1) & 3)) << 4)));
            }
#pragma unroll
            for (int p = 0; p < 2; p++) {
                int row = wn * 32 + p * 16 + brow_off;
                ldm_x4(bhf[p], aBhi + (uint32_t)(row * 64 + ((bseg ^ ((row >> 1) & 3)) << 4)));
            }
            // hi * hi
#pragma unroll
            for (int mi = 0; mi < 4; mi++)
#pragma unroll
                for (int ni = 0; ni < 4; ni++)
                    mma_bf16(acc[mi][ni], ah[mi], &bhf[ni >> 1][(ni & 1) * 2]);

            // hi * lo
            {
                uint32_t blf[2][4];
#pragma unroll
                for (int p = 0; p < 2; p++) {
                    int row = wn * 32 + p * 16 + brow_off;
                    ldm_x4(blf[p], aBlo + (uint32_t)(row * 64 + ((bseg ^ ((row >> 1) & 3)) << 4)));
                }
#pragma unroll
                for (int mi = 0; mi < 4; mi++)
#pragma unroll
                    for (int ni = 0; ni < 4; ni++)
                        mma_bf16(acc[mi][ni], ah[mi], &blf[ni >> 1][(ni & 1) * 2]);
            }
            // lo * hi
            {
                uint32_t al[4][4];
#pragma unroll
                for (int mi = 0; mi < 4; mi++) {
                    int row = wm * 64 + mi * 16 + arow_off;
                    ldm_x4(al[mi], aAlo + (uint32_t)(row * 64 + ((aseg ^ ((row >> 1) & 3)) << 4)));
                }
#pragma unroll
                for (int mi = 0; mi < 4; mi++)
#pragma unroll
                    for (int ni = 0; ni < 4; ni++)
                        mma_bf16(acc[mi][ni], al[mi], &bhf[ni >> 1][(ni & 1) * 2]);
            }
        }
    }

    // ---- epilogue: bias add + store ----
    float* __restrict__ C =
        (mode == 0) ? g_Q : (mode == 1) ? g_K : (mode == 2) ? g_V : Cout;
    const int mrb = m0 + wm * 64;
    const int ncb = n0 + wn * 32;
#pragma unroll
    for (int mi = 0; mi < 4; mi++) {
#pragma unroll
        for (int ni = 0; ni < 4; ni++) {
            int n = ncb + ni * 8 + (lane & 3) * 2;
            float2 bv = *(const float2*)&bias[n];
#pragma unroll
            for (int hf = 0; hf < 2; hf++) {
                int m = mrb + mi * 16 + (lane >> 2) + hf * 8;
                float c0 = acc[mi][ni][hf * 2 + 0] + bv.x;
                float c1 = acc[mi][ni][hf * 2 + 1] + bv.y;
                size_t addr;
                if (mode < 3) {
                    int bb = m & 1, s = m >> 1;
                    int hh = n >> 6, d = n & 63;
                    addr = (((size_t)bb * NH + hh) * SEQ + s) * DH + d;
                } else {
                    int bb = m >> 13, s = m & (SEQ - 1);
                    addr = (size_t)(s * BATCH + bb) * EMB + n;
                }
                *(float2*)&C[addr] = make_float2(c0, c1);
            }
        }
    }
}

// ============================================================
// Block-sparse attention (unchanged from R2).
// ============================================================
#define QT_OFF   0
#define KT_OFF   4096
#define VS_OFF   (KT_OFF + 8704)
#define AL_OFF   (VS_OFF + 128*68)
#define LL_OFF   (AL_OFF + 64)
#define SA_FLOATS (LL_OFF + 64)

__global__ __launch_bounds__(256, 2)
void sparse_attn(const int* __restrict__ rand_idx)
{
    extern __shared__ float sm[];
    float* Qt = sm + QT_OFF;
    float* Kt = sm + KT_OFF;
    float* Pt = sm + KT_OFF;
    float* Vs = sm + VS_OFF;
    float* alpha_s = sm + AL_OFF;
    float* l_s     = sm + LL_OFF;

    const int nb  = blockIdx.x;
    const int bh  = blockIdx.y;
    const int tid = threadIdx.x;
    const int ty   = tid >> 5;
    const int lane = tid & 31;
    const int my   = tid >> 4;
    const int nx   = tid & 15;
    const size_t base = (size_t)bh * SEQ * DH;
    const float CC = 0.18033688011112042f;

#pragma unroll
    for (int i = 0; i < 4; i++) {
        int idx = tid + 256 * i;
        int row = idx >> 4;
        int c4  = (idx & 15) * 4;
        int c   = c4 >> 2;
        float4 q = *(const float4*)&g_Q[base + (size_t)(nb * BLK + row) * DH + c4];
        int pc = (((row >> 2) ^ c) << 2) + (row & 3);
        Qt[((c4 + 0) << 6) + pc] = q.x;
        Qt[((c4 + 1) << 6) + pc] = q.y;
        Qt[((c4 + 2) << 6) + pc] = q.z;
        Qt[((c4 + 3) << 6) + pc] = q.w;
    }

    float o[4][4];
#pragma unroll
    for (int i = 0; i < 4; i++)
#pragma unroll
        for (int j = 0; j < 4; j++) o[i][j] = 0.f;
    float mst[8], lst[8];
#pragma unroll
    for (int i = 0; i < 8; i++) { mst[i] = -1e30f; lst[i] = 0.f; }

    for (int jj = 0; jj < 4; jj++) {
        int kbs[2];
#pragma unroll
        for (int t = 0; t < 2; t++) {
            int j = 2 * jj + t;
            int kb;
            if (j < NGLOB)             kb = j;
            else if (j < NGLOB + NWIN) kb = (nb + (j - NGLOB) - 1 + NBLK) & (NBLK - 1);
            else                       kb = rand_idx[nb * 3 + (j - (NGLOB + NWIN))];
            kbs[t] = kb;
        }

        __syncthreads();
#pragma unroll
        for (int i = 0; i < 8; i++) {
            int idx = tid + 256 * i;
            int key = idx >> 4;
            int c4  = (idx & 15) * 4;
            int c   = c4 >> 2;
            int kb  = (key < 64) ? kbs[0] : kbs[1];
            size_t ga = base + (size_t)(kb * BLK + (key & 63)) * DH + c4;
            float4 kv = *(const float4*)&g_K[ga];
            float4 vv = *(const float4*)&g_V[ga];
            int pc = (((key >> 2) ^ c) << 2) + (key & 3);
            Kt[((c4 + 0) << 7) + pc] = kv.x;
            Kt[((c4 + 1) << 7) + pc] = kv.y;
            Kt[((c4 + 2) << 7) + pc] = kv.z;
            Kt[((c4 + 3) << 7) + pc] = kv.w;
            *(float4*)&Vs[key * 68 + c4] = vv;
        }
        __syncthreads();

        float s[8][4];
#pragma unroll
        for (int i = 0; i < 8; i++)
#pragma unroll
            for (int j = 0; j < 4; j++) s[i][j] = 0.f;

#pragma unroll 8
        for (int d = 0; d < 64; d++) {
            int sw = (d >> 2) & 15;
            float4 q0 = *(float4*)&Qt[(d << 6) + (((2 * ty)     ^ sw) << 2)];
            float4 q1 = *(float4*)&Qt[(d << 6) + (((2 * ty + 1) ^ sw) << 2)];
            float4 kk = *(float4*)&Kt[(d << 7) + ((lane ^ sw) << 2)];
            float qa[8] = {q0.x, q0.y, q0.z, q0.w, q1.x, q1.y, q1.z, q1.w};
            float kb4[4] = {kk.x, kk.y, kk.z, kk.w};
#pragma unroll
            for (int i = 0; i < 8; i++)
#pragma unroll
                for (int j = 0; j < 4; j++)
                    s[i][j] = fmaf(qa[i], kb4[j], s[i][j]);
        }

        float alpha[8];
#pragma unroll
        for (int i = 0; i < 8; i++) {
            float mx = fmaxf(fmaxf(s[i][0], s[i][1]), fmaxf(s[i][2], s[i][3]));
#pragma unroll
            for (int off = 16; off > 0; off >>= 1)
                mx = fmaxf(mx, __shfl_xor_sync(0xffffffffu, mx, off));
            float mnew = fmaxf(mst[i], mx);
            alpha[i] = exp2f((mst[i] - mnew) * CC);
            float ls = 0.f;
#pragma unroll
            for (int j = 0; j < 4; j++) {
                s[i][j] = exp2f((s[i][j] - mnew) * CC);
                ls += s[i][j];
            }
#pragma unroll
            for (int off = 16; off > 0; off >>= 1)
                ls += __shfl_xor_sync(0xffffffffu, ls, off);
            lst[i] = lst[i] * alpha[i] + ls;
            mst[i] = mnew;
        }

        __syncthreads();

#pragma unroll
        for (int i = 0; i < 8; i++) {
            if (lane == i) {
                alpha_s[8 * ty + i] = alpha[i];
                l_s[8 * ty + i]     = lst[i];
            }
        }
#pragma unroll
        for (int j = 0; j < 4; j++) {
            float4 a = make_float4(s[0][j], s[1][j], s[2][j], s[3][j]);
            float4 b = make_float4(s[4][j], s[5][j], s[6][j], s[7][j]);
            *(float4*)&Pt[(4 * lane + j) * 68 + 8 * ty]     = a;
            *(float4*)&Pt[(4 * lane + j) * 68 + 8 * ty + 4] = b;
        }
        __syncthreads();

        float ar[4];
#pragma unroll
        for (int i = 0; i < 4; i++) ar[i] = alpha_s[4 * my + i];
#pragma unroll
        for (int i = 0; i < 4; i++)
#pragma unroll
            for (int j = 0; j < 4; j++) o[i][j] *= ar[i];

#pragma unroll 4
        for (int k = 0; k < 128; k++) {
            float4 p = *(float4*)&Pt[k * 68 + 4 * my];
            float4 v = *(float4*)&Vs[k * 68 + 4 * nx];
            float pa[4] = {p.x, p.y, p.z, p.w};
            float va[4] = {v.x, v.y, v.z, v.w};
#pragma unroll
            for (int i = 0; i < 4; i++)
#pragma unroll
                for (int j = 0; j < 4; j++)
                    o[i][j] = fmaf(pa[i], va[j], o[i][j]);
        }
    }

    const int b = bh >> 3, h = bh & 7;
#pragma unroll
    for (int i = 0; i < 4; i++) {
        float inv = 1.f / l_s[4 * my + i];
        int srow = nb * BLK + 4 * my + i;
        float4 ov;
        ov.x = o[i][0] * inv;
        ov.y = o[i][1] * inv;
        ov.z = o[i][2] * inv;
        ov.w = o[i][3] * inv;
        *(float4*)&g_AO[(size_t)(b * SEQ + srow) * EMB + h * DH + 4 * nx] = ov;
    }
}

// ============================================================
extern "C" void kernel_launch(void* const* d_in, const int* in_sizes, int n_in,
                              void* d_out, int out_size)
{
    const float* query   = (const float*)d_in[0];
    const float* key_inp = (const float*)d_in[1];
    const float* value   = (const float*)d_in[2];
    const float* q_w     = (const float*)d_in[3];
    const float* k_w     = (const float*)d_in[4];
    const float* v_w     = (const float*)d_in[5];
    const float* q_b     = (const float*)d_in[6];
    const float* k_b     = (const float*)d_in[7];
    const float* v_b     = (const float*)d_in[8];
    const float* out_w   = (const float*)d_in[9];
    const float* out_b   = (const float*)d_in[10];
    const int*   rand_idx= (const int*)d_in[11];
    float* out = (float*)d_out;

    static bool attr_set = false;
    if (!attr_set) {
        cudaFuncSetAttribute(sparse_attn,
                             cudaFuncAttributeMaxDynamicSharedMemorySize,
                             SA_FLOATS * (int)sizeof(float));
        attr_set = true;
    }

    dim3 gConv(512, 4);
    conv_weights<<<gConv, 256>>>(q_w, k_w, v_w, out_w);

    dim3 gGemm(128, 4);
    gemm_mma<<<gGemm, 256>>>(query,   q_b, out, 0);
    gemm_mma<<<gGemm, 256>>>(key_inp, k_b, out, 1);
    gemm_mma<<<gGemm, 256>>>(value,   v_b, out, 2);

    dim3 gAttn(NBLK, BATCH * NH);
    sparse_attn<<<gAttn, 256, SA_FLOATS * (int)sizeof(float)>>>(rand_idx);

    gemm_mma<<<gGemm, 256>>>(query /*ignored*/, out_b, out, 3);
}

// round 5
// speedup vs baseline: 4.4907x; 1.9725x over previous
#include <cuda_runtime.h>
#include <cuda_bf16.h>
#include <math.h>
#include <cstdint>

#define SEQ   8192
#define BATCH 2
#define EMB   512
#define NH    8
#define DH    64
#define NBLK  128      // SEQ / 64
#define BLK   64
#define MBL   8        // gathered blocks per query block
#define NGLOB 2
#define NWIN  3

// ---- device-global scratch (allocation-free) ----
__device__ float g_AO[(size_t)BATCH * SEQ * EMB];      // [(b*S+s)][e]
// Q/K/V in bf16 hi/lo split, [b][h][s][d]
__device__ __nv_bfloat16 g_Qh[(size_t)BATCH * NH * SEQ * DH];
__device__ __nv_bfloat16 g_Ql[(size_t)BATCH * NH * SEQ * DH];
__device__ __nv_bfloat16 g_Kh[(size_t)BATCH * NH * SEQ * DH];
__device__ __nv_bfloat16 g_Kl[(size_t)BATCH * NH * SEQ * DH];
__device__ __nv_bfloat16 g_Vh[(size_t)BATCH * NH * SEQ * DH];
__device__ __nv_bfloat16 g_Vl[(size_t)BATCH * NH * SEQ * DH];
// bf16 hi/lo split weights: [mat][n][k], mat: 0=q 1=k 2=v 3=out
__device__ __nv_bfloat16 g_Whi[4u * 512u * 512u];
__device__ __nv_bfloat16 g_Wlo[4u * 512u * 512u];

// ============================================================
// helpers (baseline PTX only)
// ============================================================
__device__ __forceinline__ uint32_t smem_u32(const void* p) {
    uint32_t a;
    asm("{ .reg .u64 t; cvta.to.shared.u64 t, %1; cvt.u32.u64 %0, t; }"
        : "=r"(a) : "l"(p));
    return a;
}
__device__ __forceinline__ void ldm_x4(uint32_t* r, uint32_t addr) {
    asm volatile("ldmatrix.sync.aligned.m8n8.x4.shared.b16 {%0,%1,%2,%3}, [%4];"
                 : "=r"(r[0]), "=r"(r[1]), "=r"(r[2]), "=r"(r[3]) : "r"(addr));
}
__device__ __forceinline__ void ldm_x4t(uint32_t* r, uint32_t addr) {
    asm volatile("ldmatrix.sync.aligned.m8n8.x4.trans.shared.b16 {%0,%1,%2,%3}, [%4];"
                 : "=r"(r[0]), "=r"(r[1]), "=r"(r[2]), "=r"(r[3]) : "r"(addr));
}
__device__ __forceinline__ void mma_bf16(float* d, const uint32_t* a, const uint32_t* b) {
    asm volatile(
        "mma.sync.aligned.m16n8k16.row.col.f32.bf16.bf16.f32 "
        "{%0,%1,%2,%3}, {%4,%5,%6,%7}, {%8,%9}, {%0,%1,%2,%3};"
        : "+f"(d[0]), "+f"(d[1]), "+f"(d[2]), "+f"(d[3])
        : "r"(a[0]), "r"(a[1]), "r"(a[2]), "r"(a[3]), "r"(b[0]), "r"(b[1]));
}
__device__ __forceinline__ void cp16(uint32_t dst, const void* src) {
    asm volatile("cp.async.cg.shared.global [%0], [%1], 16;" :: "r"(dst), "l"(src) : "memory");
}
__device__ __forceinline__ void cp_commit() {
    asm volatile("cp.async.commit_group;" ::: "memory");
}
template<int N> __device__ __forceinline__ void cp_wait() {
    asm volatile("cp.async.wait_group %0;" :: "n"(N) : "memory");
}
__device__ __forceinline__ uint32_t pack_bf2(float x, float y) {
    __nv_bfloat162 v = __halves2bfloat162(__float2bfloat16(x), __float2bfloat16(y));
    return *(uint32_t*)&v;
}

// ============================================================
// Weight conversion (fp32 -> bf16 hi/lo), layout [mat][n][k]
// ============================================================
__global__ void conv_weights(const float* __restrict__ qw, const float* __restrict__ kw,
                             const float* __restrict__ vw, const float* __restrict__ ow)
{
    const int mat = blockIdx.y;
    const int n   = blockIdx.x;
    const float* src = (mat == 0) ? qw : (mat == 1) ? kw : (mat == 2) ? vw : ow;
    for (int k = threadIdx.x; k < 512; k += 256) {
        float v;
        if (mat < 3) v = src[((size_t)(n >> 6) * 512 + k) * 64 + (n & 63)];
        else         v = src[(size_t)n * 512 + k];
        __nv_bfloat16 h = __float2bfloat16(v);
        __nv_bfloat16 l = __float2bfloat16(v - __bfloat162float(h));
        size_t o = (size_t)mat * 262144 + (size_t)n * 512 + k;
        g_Whi[o] = h;
        g_Wlo[o] = l;
    }
}

// ============================================================
// HMMA GEMM (bf16 hi/lo 3-term). C = A[16384x512] * W^T.
// modes 0-2: epilogue writes bf16 hi/lo Q/K/V. mode 3: fp32 out.
// ============================================================
__global__ __launch_bounds__(256, 2)
void gemm_mma(const float* __restrict__ Ain, const float* __restrict__ bias,
              float* __restrict__ Cout, int mode)
{
    __shared__ __nv_bfloat16 sAhi[128 * 32];
    __shared__ __nv_bfloat16 sAlo[128 * 32];
    __shared__ __nv_bfloat16 sBhi[128 * 32];
    __shared__ __nv_bfloat16 sBlo[128 * 32];

    const int tid  = threadIdx.x;
    const int wid  = tid >> 5;
    const int lane = tid & 31;
    const int wm   = wid >> 2;
    const int wn   = wid & 3;
    const int m0   = blockIdx.x * 128;
    const int n0   = blockIdx.y * 128;

    const float* __restrict__ A = (mode == 3) ? g_AO : Ain;
    const __nv_bfloat16* __restrict__ Bh = g_Whi + (size_t)mode * 262144;
    const __nv_bfloat16* __restrict__ Bl = g_Wlo + (size_t)mode * 262144;

    const uint32_t aAhi = smem_u32(sAhi);
    const uint32_t aAlo = smem_u32(sAlo);
    const uint32_t aBhi = smem_u32(sBhi);
    const uint32_t aBlo = smem_u32(sBlo);

    float acc[4][4][4];
#pragma unroll
    for (int i = 0; i < 4; i++)
#pragma unroll
        for (int j = 0; j < 4; j++)
#pragma unroll
            for (int r = 0; r < 4; r++) acc[i][j][r] = 0.f;

    const int tile = lane >> 3;
    const int r8   = lane & 7;

    for (int k0 = 0; k0 < 512; k0 += 32) {
        __syncthreads();
#pragma unroll
        for (int i = 0; i < 4; i++) {
            int idx = tid + 256 * i;
            int row = idx >> 3;
            int c4  = (idx & 7) * 4;
            float4 v = *(const float4*)&A[(size_t)(m0 + row) * 512 + k0 + c4];
            __nv_bfloat16 h0 = __float2bfloat16(v.x);
            __nv_bfloat16 h1 = __float2bfloat16(v.y);
            __nv_bfloat16 h2 = __float2bfloat16(v.z);
            __nv_bfloat16 h3 = __float2bfloat16(v.w);
            __nv_bfloat16 l0 = __float2bfloat16(v.x - __bfloat162float(h0));
            __nv_bfloat16 l1 = __float2bfloat16(v.y - __bfloat162float(h1));
            __nv_bfloat16 l2 = __float2bfloat16(v.z - __bfloat162float(h2));
            __nv_bfloat16 l3 = __float2bfloat16(v.w - __bfloat162float(h3));
            int seg = c4 >> 3;
            int wi  = (c4 & 4) << 1;
            uint32_t off = (uint32_t)(row * 64 + ((seg ^ ((row >> 1) & 3)) << 4) + wi);
            *(__nv_bfloat162*)((char*)sAhi + off)     = __halves2bfloat162(h0, h1);
            *(__nv_bfloat162*)((char*)sAhi + off + 4) = __halves2bfloat162(h2, h3);
            *(__nv_bfloat162*)((char*)sAlo + off)     = __halves2bfloat162(l0, l1);
            *(__nv_bfloat162*)((char*)sAlo + off + 4) = __halves2bfloat162(l2, l3);
        }
#pragma unroll
        for (int i = 0; i < 2; i++) {
            int idx = tid + 256 * i;
            int row = idx >> 2;
            int seg = idx & 3;
            uint32_t off = (uint32_t)(row * 64 + ((seg ^ ((row >> 1) & 3)) << 4));
            *(float4*)((char*)sBhi + off) = *(const float4*)&Bh[(size_t)(n0 + row) * 512 + k0 + seg * 8];
            *(float4*)((char*)sBlo + off) = *(const float4*)&Bl[(size_t)(n0 + row) * 512 + k0 + seg * 8];
        }
        __syncthreads();

#pragma unroll
        for (int ks = 0; ks < 2; ks++) {
            const int k16 = ks * 16;
            const int arow_off = r8 + ((tile & 1) << 3);
            const int aseg = (k16 + ((tile >= 2) ? 8 : 0)) >> 3;
            const int brow_off = r8 + ((tile >> 1) << 3);
            const int bseg = (k16 + ((tile & 1) ? 8 : 0)) >> 3;

            uint32_t ah[4][4], bhf[2][4];
#pragma unroll
            for (int mi = 0; mi < 4; mi++) {
                int row = wm * 64 + mi * 16 + arow_off;
                ldm_x4(ah[mi], aAhi + (uint32_t)(row * 64 + ((aseg ^ ((row >> 1) & 3)) << 4)));
            }
#pragma unroll
            for (int p = 0; p < 2; p++) {
                int row = wn * 32 + p * 16 + brow_off;
                ldm_x4(bhf[p], aBhi + (uint32_t)(row * 64 + ((bseg ^ ((row >> 1) & 3)) << 4)));
            }
#pragma unroll
            for (int mi = 0; mi < 4; mi++)
#pragma unroll
                for (int ni = 0; ni < 4; ni++)
                    mma_bf16(acc[mi][ni], ah[mi], &bhf[ni >> 1][(ni & 1) * 2]);
            {
                uint32_t blf[2][4];
#pragma unroll
                for (int p = 0; p < 2; p++) {
                    int row = wn * 32 + p * 16 + brow_off;
                    ldm_x4(blf[p], aBlo + (uint32_t)(row * 64 + ((bseg ^ ((row >> 1) & 3)) << 4)));
                }
#pragma unroll
                for (int mi = 0; mi < 4; mi++)
#pragma unroll
                    for (int ni = 0; ni < 4; ni++)
                        mma_bf16(acc[mi][ni], ah[mi], &blf[ni >> 1][(ni & 1) * 2]);
            }
            {
                uint32_t al[4][4];
#pragma unroll
                for (int mi = 0; mi < 4; mi++) {
                    int row = wm * 64 + mi * 16 + arow_off;
                    ldm_x4(al[mi], aAlo + (uint32_t)(row * 64 + ((aseg ^ ((row >> 1) & 3)) << 4)));
                }
#pragma unroll
                for (int mi = 0; mi < 4; mi++)
#pragma unroll
                    for (int ni = 0; ni < 4; ni++)
                        mma_bf16(acc[mi][ni], al[mi], &bhf[ni >> 1][(ni & 1) * 2]);
            }
        }
    }

    // ---- epilogue ----
    const int mrb = m0 + wm * 64;
    const int ncb = n0 + wn * 32;
#pragma unroll
    for (int mi = 0; mi < 4; mi++) {
#pragma unroll
        for (int ni = 0; ni < 4; ni++) {
            int n = ncb + ni * 8 + (lane & 3) * 2;
            float2 bv = *(const float2*)&bias[n];
#pragma unroll
            for (int hf = 0; hf < 2; hf++) {
                int m = mrb + mi * 16 + (lane >> 2) + hf * 8;
                float c0 = acc[mi][ni][hf * 2 + 0] + bv.x;
                float c1 = acc[mi][ni][hf * 2 + 1] + bv.y;
                if (mode < 3) {
                    int bb = m & 1, s = m >> 1;
                    int hh = n >> 6, d = n & 63;
                    size_t addr = (((size_t)bb * NH + hh) * SEQ + s) * DH + d;
                    __nv_bfloat16 h0 = __float2bfloat16(c0);
                    __nv_bfloat16 h1 = __float2bfloat16(c1);
                    __nv_bfloat16 e0 = __float2bfloat16(c0 - __bfloat162float(h0));
                    __nv_bfloat16 e1 = __float2bfloat16(c1 - __bfloat162float(h1));
                    __nv_bfloat16* Ch = (mode == 0) ? g_Qh : (mode == 1) ? g_Kh : g_Vh;
                    __nv_bfloat16* Cl = (mode == 0) ? g_Ql : (mode == 1) ? g_Kl : g_Vl;
                    *(__nv_bfloat162*)&Ch[addr] = __halves2bfloat162(h0, h1);
                    *(__nv_bfloat162*)&Cl[addr] = __halves2bfloat162(e0, e1);
                } else {
                    int bb = m >> 13, s = m & (SEQ - 1);
                    *(float2*)&Cout[(size_t)(s * BATCH + bb) * EMB + n] = make_float2(c0, c1);
                }
            }
        }
    }
}

// ============================================================
// Tensor-core block-sparse attention.
// Grid (NBLK, BATCH*NH), 256 thr, 8 warps: wm=wid>>1 (q 16-rows), wn=wid&1 (keys 32).
// Smem: Qh/Ql (16KB) + 2-stage KV (2x32KB) + stats. cp.async pipeline.
// ============================================================
#define AT_QH    0
#define AT_QL    8192
#define AT_STG0  16384
#define AT_STGSZ 32768
#define AT_KH    0
#define AT_KL    8192
#define AT_VH    16384
#define AT_VL    24576
#define AT_STATS 81920
#define AT_SMEM  (AT_STATS + 448 * 4)

__device__ __forceinline__ int blk_of(int j, int nb, const int* __restrict__ ri) {
    if (j < NGLOB) return j;
    if (j < NGLOB + NWIN) return (nb + j - 3 + NBLK) & (NBLK - 1);
    return ri[nb * 3 + (j - 5)];
}

__global__ __launch_bounds__(256, 2)
void attn_mma(const int* __restrict__ rand_idx)
{
    extern __shared__ char smb[];
    const uint32_t sb = smem_u32(smb);
    float* stats   = (float*)(smb + AT_STATS);
    float* m_s     = stats;
    float* l_s     = stats + 64;
    float* alpha_s = stats + 128;
    float* pmax    = stats + 192;   // [2][64]
    float* psum    = stats + 320;   // [2][64]

    const int nb  = blockIdx.x;
    const int bh  = blockIdx.y;
    const int tid = threadIdx.x;
    const int wid  = tid >> 5;
    const int lane = tid & 31;
    const int wm = wid >> 1;
    const int wn = wid & 1;
    const int tile = lane >> 3;
    const int r8   = lane & 7;
    const int qrow = lane >> 2;          // 0..7
    const int qc   = (lane & 3) * 2;
    const size_t base = (size_t)bh * SEQ * DH;
    const float CC = 0.18033688011112042f;   // (1/8) * log2(e)

    if (tid < 64) { m_s[tid] = -1e30f; l_s[tid] = 0.f; }

    // ---- stage Q (hi/lo) + KV block 0 via cp.async (group 0) ----
#pragma unroll
    for (int i = 0; i < 4; i++) {
        int idx = tid + 256 * i;              // 0..1023
        int mq  = idx >> 9;
        int row = (idx >> 3) & 63;
        int seg = idx & 7;
        const __nv_bfloat16* src = (mq ? g_Ql : g_Qh) + base + (size_t)(nb * BLK + row) * DH + seg * 8;
        uint32_t dst = sb + (mq ? AT_QL : AT_QH) + row * 128 + ((seg ^ (row & 7)) << 4);
        cp16(dst, src);
    }
    {
        int kb = blk_of(0, nb, rand_idx);
        size_t kvb = base + (size_t)kb * BLK * DH;
#pragma unroll
        for (int i = 0; i < 8; i++) {
            int idx = tid + 256 * i;          // 0..2047
            int mat = idx >> 9;               // 0=Kh 1=Kl 2=Vh 3=Vl
            int row = (idx >> 3) & 63;
            int seg = idx & 7;
            const __nv_bfloat16* mb = (mat & 2) ? ((mat & 1) ? g_Vl : g_Vh)
                                                : ((mat & 1) ? g_Kl : g_Kh);
            uint32_t dst = sb + AT_STG0 + mat * 8192 + row * 128 + ((seg ^ (row & 7)) << 4);
            cp16(dst, mb + kvb + row * 64 + seg * 8);
        }
    }
    cp_commit();

    float of[8][4];
#pragma unroll
    for (int i = 0; i < 8; i++)
#pragma unroll
        for (int j = 0; j < 4; j++) of[i][j] = 0.f;

    for (int j = 0; j < MBL; j++) {
        // prefetch next KV block
        if (j + 1 < MBL) {
            int kb = blk_of(j + 1, nb, rand_idx);
            size_t kvb = base + (size_t)kb * BLK * DH;
            uint32_t stg = sb + AT_STG0 + ((j + 1) & 1) * AT_STGSZ;
#pragma unroll
            for (int i = 0; i < 8; i++) {
                int idx = tid + 256 * i;
                int mat = idx >> 9;
                int row = (idx >> 3) & 63;
                int seg = idx & 7;
                const __nv_bfloat16* mb = (mat & 2) ? ((mat & 1) ? g_Vl : g_Vh)
                                                    : ((mat & 1) ? g_Kl : g_Kh);
                uint32_t dst = stg + mat * 8192 + row * 128 + ((seg ^ (row & 7)) << 4);
                cp16(dst, mb + kvb + row * 64 + seg * 8);
            }
            cp_commit();
            cp_wait<1>();
        } else {
            cp_wait<0>();
        }
        __syncthreads();

        const uint32_t stg = sb + AT_STG0 + (j & 1) * AT_STGSZ;

        // ---- QK^T: S frags (4 n8-frags over warp's 32 keys) ----
        float sf[4][4];
#pragma unroll
        for (int nf = 0; nf < 4; nf++)
#pragma unroll
            for (int r = 0; r < 4; r++) sf[nf][r] = 0.f;

#pragma unroll
        for (int ks = 0; ks < 4; ks++) {
            const int arow = 16 * wm + r8 + ((tile & 1) << 3);
            const int aseg = ks * 2 + ((tile >> 1) & 1);
            const uint32_t aoff = (uint32_t)(arow * 128 + ((aseg ^ (arow & 7)) << 4));
            uint32_t qh[4], ql[4];
            ldm_x4(qh, sb + AT_QH + aoff);
            ldm_x4(ql, sb + AT_QL + aoff);

            uint32_t kh[2][4], kl[2][4];
#pragma unroll
            for (int p = 0; p < 2; p++) {
                const int brow = 32 * wn + 16 * p + r8 + ((tile >> 1) << 3);
                const int bseg = ks * 2 + (tile & 1);
                const uint32_t boff = (uint32_t)(brow * 128 + ((bseg ^ (brow & 7)) << 4));
                ldm_x4(kh[p], stg + AT_KH + boff);
                ldm_x4(kl[p], stg + AT_KL + boff);
            }
#pragma unroll
            for (int nf = 0; nf < 4; nf++)
                mma_bf16(sf[nf], qh, &kh[nf >> 1][(nf & 1) * 2]);
#pragma unroll
            for (int nf = 0; nf < 4; nf++)
                mma_bf16(sf[nf], qh, &kl[nf >> 1][(nf & 1) * 2]);
#pragma unroll
            for (int nf = 0; nf < 4; nf++)
                mma_bf16(sf[nf], ql, &kh[nf >> 1][(nf & 1) * 2]);
        }

        // ---- partial row max ----
        float rmax0 = sf[0][0], rmax1 = sf[0][2];
#pragma unroll
        for (int nf = 0; nf < 4; nf++) {
            rmax0 = fmaxf(rmax0, fmaxf(sf[nf][0], sf[nf][1]));
            rmax1 = fmaxf(rmax1, fmaxf(sf[nf][2], sf[nf][3]));
        }
        rmax0 = fmaxf(rmax0, __shfl_xor_sync(0xffffffffu, rmax0, 1));
        rmax0 = fmaxf(rmax0, __shfl_xor_sync(0xffffffffu, rmax0, 2));
        rmax1 = fmaxf(rmax1, __shfl_xor_sync(0xffffffffu, rmax1, 1));
        rmax1 = fmaxf(rmax1, __shfl_xor_sync(0xffffffffu, rmax1, 2));
        if ((lane & 3) == 0) {
            pmax[wn * 64 + 16 * wm + qrow]     = rmax0;
            pmax[wn * 64 + 16 * wm + qrow + 8] = rmax1;
        }
        __syncthreads();

        if (tid < 64) {
            float mo = m_s[tid];
            float mn = fmaxf(mo, fmaxf(pmax[tid], pmax[64 + tid]));
            float al = exp2f((mo - mn) * CC);
            m_s[tid] = mn;
            alpha_s[tid] = al;
            l_s[tid] *= al;
        }
        __syncthreads();

        // ---- exp, P frags (hi/lo in registers), row sums, O rescale ----
        const int r0 = 16 * wm + qrow;
        const float mn0 = m_s[r0], mn1 = m_s[r0 + 8];
        const float al0 = alpha_s[r0], al1 = alpha_s[r0 + 8];

        float rsum0 = 0.f, rsum1 = 0.f;
        uint32_t pah[2][4], pal[2][4];
#pragma unroll
        for (int t = 0; t < 2; t++) {
#pragma unroll
            for (int hl = 0; hl < 2; hl++) {
                int nf = 2 * t + hl;
                float p0 = exp2f((sf[nf][0] - mn0) * CC);
                float p1 = exp2f((sf[nf][1] - mn0) * CC);
                float p2 = exp2f((sf[nf][2] - mn1) * CC);
                float p3 = exp2f((sf[nf][3] - mn1) * CC);
                rsum0 += p0 + p1;
                rsum1 += p2 + p3;
                uint32_t h01 = pack_bf2(p0, p1);
                uint32_t h23 = pack_bf2(p2, p3);
                __nv_bfloat162 hv01 = *(__nv_bfloat162*)&h01;
                __nv_bfloat162 hv23 = *(__nv_bfloat162*)&h23;
                uint32_t l01 = pack_bf2(p0 - __bfloat162float(hv01.x),
                                        p1 - __bfloat162float(hv01.y));
                uint32_t l23 = pack_bf2(p2 - __bfloat162float(hv23.x),
                                        p3 - __bfloat162float(hv23.y));
                pah[t][2 * hl + 0] = h01;
                pah[t][2 * hl + 1] = h23;
                pal[t][2 * hl + 0] = l01;
                pal[t][2 * hl + 1] = l23;
            }
        }
        rsum0 += __shfl_xor_sync(0xffffffffu, rsum0, 1);
        rsum0 += __shfl_xor_sync(0xffffffffu, rsum0, 2);
        rsum1 += __shfl_xor_sync(0xffffffffu, rsum1, 1);
        rsum1 += __shfl_xor_sync(0xffffffffu, rsum1, 2);
        if ((lane & 3) == 0) {
            psum[wn * 64 + r0]     = rsum0;
            psum[wn * 64 + r0 + 8] = rsum1;
        }
#pragma unroll
        for (int nf = 0; nf < 8; nf++) {
            of[nf][0] *= al0; of[nf][1] *= al0;
            of[nf][2] *= al1; of[nf][3] *= al1;
        }

        // ---- PV: O += P * V (3-term) ----
#pragma unroll
        for (int t = 0; t < 2; t++) {
            const int sel = lane >> 3;
            const int vkey = 32 * wn + 16 * t + (lane & 7) + ((sel & 1) << 3);
#pragma unroll
            for (int g = 0; g < 4; g++) {
                const int vseg = 2 * g + (sel >> 1);
                const uint32_t voff = (uint32_t)(vkey * 128 + ((vseg ^ (vkey & 7)) << 4));
                uint32_t vh[4], vl[4];
                ldm_x4t(vh, stg + AT_VH + voff);
                ldm_x4t(vl, stg + AT_VL + voff);
                mma_bf16(of[2 * g + 0], pah[t], &vh[0]);
                mma_bf16(of[2 * g + 1], pah[t], &vh[2]);
                mma_bf16(of[2 * g + 0], pal[t], &vh[0]);
                mma_bf16(of[2 * g + 1], pal[t], &vh[2]);
                mma_bf16(of[2 * g + 0], pah[t], &vl[0]);
                mma_bf16(of[2 * g + 1], pah[t], &vl[2]);
            }
        }
        __syncthreads();
        if (tid < 64) l_s[tid] += psum[tid] + psum[64 + tid];
    }
    __syncthreads();

    // ---- final: reduce the two wn partials, divide by l, store ----
    float* Os = (float*)(smb + AT_STG0);    // [64][68]
    const int r0 = 16 * wm + qrow;
    if (wn == 1) {
#pragma unroll
        for (int nf = 0; nf < 8; nf++) {
            int d = nf * 8 + qc;
            *(float2*)&Os[r0 * 68 + d]       = make_float2(of[nf][0], of[nf][1]);
            *(float2*)&Os[(r0 + 8) * 68 + d] = make_float2(of[nf][2], of[nf][3]);
        }
    }
    __syncthreads();
    if (wn == 0) {
        const int b = bh >> 3, h = bh & 7;
        const float inv0 = 1.f / l_s[r0];
        const float inv1 = 1.f / l_s[r0 + 8];
#pragma unroll
        for (int nf = 0; nf < 8; nf++) {
            int d = nf * 8 + qc;
            float2 t0 = *(float2*)&Os[r0 * 68 + d];
            float2 t1 = *(float2*)&Os[(r0 + 8) * 68 + d];
            size_t a0 = (size_t)(b * SEQ + nb * BLK + r0) * EMB + h * DH + d;
            size_t a1 = (size_t)(b * SEQ + nb * BLK + r0 + 8) * EMB + h * DH + d;
            *(float2*)&g_AO[a0] = make_float2((of[nf][0] + t0.x) * inv0,
                                              (of[nf][1] + t0.y) * inv0);
            *(float2*)&g_AO[a1] = make_float2((of[nf][2] + t1.x) * inv1,
                                              (of[nf][3] + t1.y) * inv1);
        }
    }
}

// ============================================================
extern "C" void kernel_launch(void* const* d_in, const int* in_sizes, int n_in,
                              void* d_out, int out_size)
{
    const float* query   = (const float*)d_in[0];
    const float* key_inp = (const float*)d_in[1];
    const float* value   = (const float*)d_in[2];
    const float* q_w     = (const float*)d_in[3];
    const float* k_w     = (const float*)d_in[4];
    const float* v_w     = (const float*)d_in[5];
    const float* q_b     = (const float*)d_in[6];
    const float* k_b     = (const float*)d_in[7];
    const float* v_b     = (const float*)d_in[8];
    const float* out_w   = (const float*)d_in[9];
    const float* out_b   = (const float*)d_in[10];
    const int*   rand_idx= (const int*)d_in[11];
    float* out = (float*)d_out;

    static bool attr_set = false;
    if (!attr_set) {
        cudaFuncSetAttribute(attn_mma,
                             cudaFuncAttributeMaxDynamicSharedMemorySize, AT_SMEM);
        attr_set = true;
    }

    dim3 gConv(512, 4);
    conv_weights<<<gConv, 256>>>(q_w, k_w, v_w, out_w);

    dim3 gGemm(128, 4);
    gemm_mma<<<gGemm, 256>>>(query,   q_b, out, 0);
    gemm_mma<<<gGemm, 256>>>(key_inp, k_b, out, 1);
    gemm_mma<<<gGemm, 256>>>(value,   v_b, out, 2);

    dim3 gAttn(NBLK, BATCH * NH);
    attn_mma<<<gAttn, 256, AT_SMEM>>>(rand_idx);

    gemm_mma<<<gGemm, 256>>>(query /*ignored*/, out_b, out, 3);
}

// round 6
// speedup vs baseline: 4.8004x; 1.0690x over previous
#include <cuda_runtime.h>
#include <cuda_bf16.h>
#include <math.h>
#include <cstdint>

#define SEQ   8192
#define BATCH 2
#define EMB   512
#define NH    8
#define DH    64
#define NBLK  128      // SEQ / 64
#define BLK   64
#define MBL   8        // gathered blocks per query block
#define NGLOB 2
#define NWIN  3

#define IN_STRIDE ((size_t)16384 * 512)

// ---- device-global scratch (allocation-free) ----
// A-side activations, bf16 hi/lo: slots 0=q_in 1=k_in 2=v_in 3=attn_out
__device__ __nv_bfloat16 g_Inh[4 * IN_STRIDE];
__device__ __nv_bfloat16 g_Inl[4 * IN_STRIDE];
// Q/K/V (post-projection) bf16 hi/lo, [b][h][s][d]
__device__ __nv_bfloat16 g_Qh[(size_t)BATCH * NH * SEQ * DH];
__device__ __nv_bfloat16 g_Ql[(size_t)BATCH * NH * SEQ * DH];
__device__ __nv_bfloat16 g_Kh[(size_t)BATCH * NH * SEQ * DH];
__device__ __nv_bfloat16 g_Kl[(size_t)BATCH * NH * SEQ * DH];
__device__ __nv_bfloat16 g_Vh[(size_t)BATCH * NH * SEQ * DH];
__device__ __nv_bfloat16 g_Vl[(size_t)BATCH * NH * SEQ * DH];
// bf16 hi/lo split weights: [mat][n][k], mat: 0=q 1=k 2=v 3=out
__device__ __nv_bfloat16 g_Whi[4u * 512u * 512u];
__device__ __nv_bfloat16 g_Wlo[4u * 512u * 512u];

// ============================================================
// helpers (baseline PTX only)
// ============================================================
__device__ __forceinline__ uint32_t smem_u32(const void* p) {
    uint32_t a;
    asm("{ .reg .u64 t; cvta.to.shared.u64 t, %1; cvt.u32.u64 %0, t; }"
        : "=r"(a) : "l"(p));
    return a;
}
__device__ __forceinline__ void ldm_x4(uint32_t* r, uint32_t addr) {
    asm volatile("ldmatrix.sync.aligned.m8n8.x4.shared.b16 {%0,%1,%2,%3}, [%4];"
                 : "=r"(r[0]), "=r"(r[1]), "=r"(r[2]), "=r"(r[3]) : "r"(addr));
}
__device__ __forceinline__ void ldm_x4t(uint32_t* r, uint32_t addr) {
    asm volatile("ldmatrix.sync.aligned.m8n8.x4.trans.shared.b16 {%0,%1,%2,%3}, [%4];"
                 : "=r"(r[0]), "=r"(r[1]), "=r"(r[2]), "=r"(r[3]) : "r"(addr));
}
__device__ __forceinline__ void mma_bf16(float* d, const uint32_t* a, const uint32_t* b) {
    asm volatile(
        "mma.sync.aligned.m16n8k16.row.col.f32.bf16.bf16.f32 "
        "{%0,%1,%2,%3}, {%4,%5,%6,%7}, {%8,%9}, {%0,%1,%2,%3};"
        : "+f"(d[0]), "+f"(d[1]), "+f"(d[2]), "+f"(d[3])
        : "r"(a[0]), "r"(a[1]), "r"(a[2]), "r"(a[3]), "r"(b[0]), "r"(b[1]));
}
__device__ __forceinline__ void cp16(uint32_t dst, const void* src) {
    asm volatile("cp.async.cg.shared.global [%0], [%1], 16;" :: "r"(dst), "l"(src) : "memory");
}
__device__ __forceinline__ void cp_commit() {
    asm volatile("cp.async.commit_group;" ::: "memory");
}
template<int N> __device__ __forceinline__ void cp_wait() {
    asm volatile("cp.async.wait_group %0;" :: "n"(N) : "memory");
}
__device__ __forceinline__ uint32_t pack_bf2(float x, float y) {
    __nv_bfloat162 v = __halves2bfloat162(__float2bfloat16(x), __float2bfloat16(y));
    return *(uint32_t*)&v;
}

// ============================================================
// Weight conversion (fp32 -> bf16 hi/lo), layout [mat][n][k]
// ============================================================
__global__ void conv_weights(const float* __restrict__ qw, const float* __restrict__ kw,
                             const float* __restrict__ vw, const float* __restrict__ ow)
{
    const int mat = blockIdx.y;
    const int n   = blockIdx.x;
    const float* src = (mat == 0) ? qw : (mat == 1) ? kw : (mat == 2) ? vw : ow;
    for (int k = threadIdx.x; k < 512; k += 256) {
        float v;
        if (mat < 3) v = src[((size_t)(n >> 6) * 512 + k) * 64 + (n & 63)];
        else         v = src[(size_t)n * 512 + k];
        __nv_bfloat16 h = __float2bfloat16(v);
        __nv_bfloat16 l = __float2bfloat16(v - __bfloat162float(h));
        size_t o = (size_t)mat * 262144 + (size_t)n * 512 + k;
        g_Whi[o] = h;
        g_Wlo[o] = l;
    }
}

// ============================================================
// Input conversion (fp32 -> bf16 hi/lo), mats 0-2, linear layout.
// ============================================================
__global__ void conv_inputs(const float* __restrict__ q, const float* __restrict__ k,
                            const float* __restrict__ v)
{
    const int mat = blockIdx.y;
    const float* src = (mat == 0) ? q : (mat == 1) ? k : v;
    __nv_bfloat16* dh = g_Inh + (size_t)mat * IN_STRIDE;
    __nv_bfloat16* dl = g_Inl + (size_t)mat * IN_STRIDE;
#pragma unroll
    for (int i = 0; i < 4; i++) {
        size_t o4 = (size_t)blockIdx.x * 1024 + i * 256 + threadIdx.x;   // float4 idx
        float4 x = *(const float4*)&src[o4 * 4];
        __nv_bfloat16 h0 = __float2bfloat16(x.x);
        __nv_bfloat16 h1 = __float2bfloat16(x.y);
        __nv_bfloat16 h2 = __float2bfloat16(x.z);
        __nv_bfloat16 h3 = __float2bfloat16(x.w);
        __nv_bfloat16 l0 = __float2bfloat16(x.x - __bfloat162float(h0));
        __nv_bfloat16 l1 = __float2bfloat16(x.y - __bfloat162float(h1));
        __nv_bfloat16 l2 = __float2bfloat16(x.z - __bfloat162float(h2));
        __nv_bfloat16 l3 = __float2bfloat16(x.w - __bfloat162float(h3));
        *(__nv_bfloat162*)&dh[o4 * 4 + 0] = __halves2bfloat162(h0, h1);
        *(__nv_bfloat162*)&dh[o4 * 4 + 2] = __halves2bfloat162(h2, h3);
        *(__nv_bfloat162*)&dl[o4 * 4 + 0] = __halves2bfloat162(l0, l1);
        *(__nv_bfloat162*)&dl[o4 * 4 + 2] = __halves2bfloat162(l2, l3);
    }
}

// ============================================================
// HMMA GEMM, bf16 hi/lo 3-term, 3-stage cp.async pipeline.
// C = A[16384x512] * W^T. CTA tile 128x128, BK=32.
// Grid (128, 4*nmats): mode = mode_base + (by>>2), n0 = (by&3)*128.
// modes 0-2 write Q/K/V hi/lo; mode 3 writes fp32 Cout.
// ============================================================
#define GS_STAGE 32768
#define GS_SMEM  (3 * GS_STAGE)

__global__ __launch_bounds__(256, 2)
void gemm_mma(const float* __restrict__ qb, const float* __restrict__ kb,
              const float* __restrict__ vb, const float* __restrict__ ob,
              float* __restrict__ Cout, int mode_base)
{
    extern __shared__ char gsm[];
    const uint32_t sb = smem_u32(gsm);
    const int tid  = threadIdx.x;
    const int wid  = tid >> 5;
    const int lane = tid & 31;
    const int wm   = wid >> 2;
    const int wn   = wid & 3;
    const int m0   = blockIdx.x * 128;
    const int mode = mode_base + (blockIdx.y >> 2);
    const int n0   = (blockIdx.y & 3) * 128;

    const __nv_bfloat16* __restrict__ Ah = g_Inh + (size_t)mode * IN_STRIDE;
    const __nv_bfloat16* __restrict__ Al = g_Inl + (size_t)mode * IN_STRIDE;
    const __nv_bfloat16* __restrict__ Bh = g_Whi + (size_t)mode * 262144;
    const __nv_bfloat16* __restrict__ Bl = g_Wlo + (size_t)mode * 262144;
    const float* __restrict__ bias = (mode == 0) ? qb : (mode == 1) ? kb
                                   : (mode == 2) ? vb : ob;

    // stage layout: Ah 0-8K, Al 8-16K, Bh 16-24K, Bl 24-32K
#define GPREFETCH(K0, ST)                                                        \
    {                                                                            \
        uint32_t d0 = sb + (ST) * GS_STAGE;                                      \
        _Pragma("unroll")                                                        \
        for (int i = 0; i < 8; i++) {                                            \
            int idx = tid + 256 * i;                                             \
            int mt  = idx >> 9;                                                  \
            int row = (idx >> 2) & 127;                                          \
            int seg = idx & 3;                                                   \
            const __nv_bfloat16* src =                                           \
                (mt == 0) ? Ah + (size_t)(m0 + row) * 512 + (K0) + seg * 8 :     \
                (mt == 1) ? Al + (size_t)(m0 + row) * 512 + (K0) + seg * 8 :     \
                (mt == 2) ? Bh + (size_t)(n0 + row) * 512 + (K0) + seg * 8 :     \
                            Bl + (size_t)(n0 + row) * 512 + (K0) + seg * 8;      \
            cp16(d0 + mt * 8192 + row * 64 + ((seg ^ ((row >> 1) & 3)) << 4),    \
                 src);                                                           \
        }                                                                        \
    }

    GPREFETCH(0, 0);  cp_commit();
    GPREFETCH(32, 1); cp_commit();

    float acc[4][4][4];
#pragma unroll
    for (int i = 0; i < 4; i++)
#pragma unroll
        for (int j = 0; j < 4; j++)
#pragma unroll
            for (int r = 0; r < 4; r++) acc[i][j][r] = 0.f;

    const int tile = lane >> 3;
    const int r8   = lane & 7;

    for (int it = 0; it < 16; it++) {
        if (it < 15) cp_wait<1>(); else cp_wait<0>();
        __syncthreads();
        if (it + 2 < 16) {
            int st = (it + 2) % 3;
            GPREFETCH((it + 2) * 32, st);
            cp_commit();
        }
        const uint32_t stg  = sb + (it % 3) * GS_STAGE;
        const uint32_t aAhi = stg;
        const uint32_t aAlo = stg + 8192;
        const uint32_t aBhi = stg + 16384;
        const uint32_t aBlo = stg + 24576;

#pragma unroll
        for (int ks = 0; ks < 2; ks++) {
            const int k16 = ks * 16;
            const int arow_off = r8 + ((tile & 1) << 3);
            const int aseg = (k16 + ((tile >= 2) ? 8 : 0)) >> 3;
            const int brow_off = r8 + ((tile >> 1) << 3);
            const int bseg = (k16 + ((tile & 1) ? 8 : 0)) >> 3;

            uint32_t ah[4][4], bhf[2][4];
#pragma unroll
            for (int mi = 0; mi < 4; mi++) {
                int row = wm * 64 + mi * 16 + arow_off;
                ldm_x4(ah[mi], aAhi + (uint32_t)(row * 64 + ((aseg ^ ((row >> 1) & 3)) << 4)));
            }
#pragma unroll
            for (int p = 0; p < 2; p++) {
                int row = wn * 32 + p * 16 + brow_off;
                ldm_x4(bhf[p], aBhi + (uint32_t)(row * 64 + ((bseg ^ ((row >> 1) & 3)) << 4)));
            }
#pragma unroll
            for (int mi = 0; mi < 4; mi++)
#pragma unroll
                for (int ni = 0; ni < 4; ni++)
                    mma_bf16(acc[mi][ni], ah[mi], &bhf[ni >> 1][(ni & 1) * 2]);
            {
                uint32_t blf[2][4];
#pragma unroll
                for (int p = 0; p < 2; p++) {
                    int row = wn * 32 + p * 16 + brow_off;
                    ldm_x4(blf[p], aBlo + (uint32_t)(row * 64 + ((bseg ^ ((row >> 1) & 3)) << 4)));
                }
#pragma unroll
                for (int mi = 0; mi < 4; mi++)
#pragma unroll
                    for (int ni = 0; ni < 4; ni++)
                        mma_bf16(acc[mi][ni], ah[mi], &blf[ni >> 1][(ni & 1) * 2]);
            }
            {
                uint32_t al[4][4];
#pragma unroll
                for (int mi = 0; mi < 4; mi++) {
                    int row = wm * 64 + mi * 16 + arow_off;
                    ldm_x4(al[mi], aAlo + (uint32_t)(row * 64 + ((aseg ^ ((row >> 1) & 3)) << 4)));
                }
#pragma unroll
                for (int mi = 0; mi < 4; mi++)
#pragma unroll
                    for (int ni = 0; ni < 4; ni++)
                        mma_bf16(acc[mi][ni], al[mi], &bhf[ni >> 1][(ni & 1) * 2]);
            }
        }
        __syncthreads();
    }

    // ---- epilogue ----
    const int mrb = m0 + wm * 64;
    const int ncb = n0 + wn * 32;
#pragma unroll
    for (int mi = 0; mi < 4; mi++) {
#pragma unroll
        for (int ni = 0; ni < 4; ni++) {
            int n = ncb + ni * 8 + (lane & 3) * 2;
            float2 bv = *(const float2*)&bias[n];
#pragma unroll
            for (int hf = 0; hf < 2; hf++) {
                int m = mrb + mi * 16 + (lane >> 2) + hf * 8;
                float c0 = acc[mi][ni][hf * 2 + 0] + bv.x;
                float c1 = acc[mi][ni][hf * 2 + 1] + bv.y;
                if (mode < 3) {
                    int bb = m & 1, s = m >> 1;
                    int hh = n >> 6, d = n & 63;
                    size_t addr = (((size_t)bb * NH + hh) * SEQ + s) * DH + d;
                    __nv_bfloat16 h0 = __float2bfloat16(c0);
                    __nv_bfloat16 h1 = __float2bfloat16(c1);
                    __nv_bfloat16 e0 = __float2bfloat16(c0 - __bfloat162float(h0));
                    __nv_bfloat16 e1 = __float2bfloat16(c1 - __bfloat162float(h1));
                    __nv_bfloat16* Ch = (mode == 0) ? g_Qh : (mode == 1) ? g_Kh : g_Vh;
                    __nv_bfloat16* Cl = (mode == 0) ? g_Ql : (mode == 1) ? g_Kl : g_Vl;
                    *(__nv_bfloat162*)&Ch[addr] = __halves2bfloat162(h0, h1);
                    *(__nv_bfloat162*)&Cl[addr] = __halves2bfloat162(e0, e1);
                } else {
                    int bb = m >> 13, s = m & (SEQ - 1);
                    *(float2*)&Cout[(size_t)(s * BATCH + bb) * EMB + n] = make_float2(c0, c1);
                }
            }
        }
    }
#undef GPREFETCH
}

// ============================================================
// Tensor-core block-sparse attention (R5, epilogue -> bf16 hi/lo AO).
// ============================================================
#define AT_QH    0
#define AT_QL    8192
#define AT_STG0  16384
#define AT_STGSZ 32768
#define AT_KH    0
#define AT_KL    8192
#define AT_VH    16384
#define AT_VL    24576
#define AT_STATS 81920
#define AT_SMEM  (AT_STATS + 448 * 4)

__device__ __forceinline__ int blk_of(int j, int nb, const int* __restrict__ ri) {
    if (j < NGLOB) return j;
    if (j < NGLOB + NWIN) return (nb + j - 3 + NBLK) & (NBLK - 1);
    return ri[nb * 3 + (j - 5)];
}

__global__ __launch_bounds__(256, 2)
void attn_mma(const int* __restrict__ rand_idx)
{
    extern __shared__ char smb[];
    const uint32_t sb = smem_u32(smb);
    float* stats   = (float*)(smb + AT_STATS);
    float* m_s     = stats;
    float* l_s     = stats + 64;
    float* alpha_s = stats + 128;
    float* pmax    = stats + 192;   // [2][64]
    float* psum    = stats + 320;   // [2][64]

    const int nb  = blockIdx.x;
    const int bh  = blockIdx.y;
    const int tid = threadIdx.x;
    const int wid  = tid >> 5;
    const int lane = tid & 31;
    const int wm = wid >> 1;
    const int wn = wid & 1;
    const int tile = lane >> 3;
    const int r8   = lane & 7;
    const int qrow = lane >> 2;
    const int qc   = (lane & 3) * 2;
    const size_t base = (size_t)bh * SEQ * DH;
    const float CC = 0.18033688011112042f;

    if (tid < 64) { m_s[tid] = -1e30f; l_s[tid] = 0.f; }

#pragma unroll
    for (int i = 0; i < 4; i++) {
        int idx = tid + 256 * i;
        int mq  = idx >> 9;
        int row = (idx >> 3) & 63;
        int seg = idx & 7;
        const __nv_bfloat16* src = (mq ? g_Ql : g_Qh) + base + (size_t)(nb * BLK + row) * DH + seg * 8;
        uint32_t dst = sb + (mq ? AT_QL : AT_QH) + row * 128 + ((seg ^ (row & 7)) << 4);
        cp16(dst, src);
    }
    {
        int kb = blk_of(0, nb, rand_idx);
        size_t kvb = base + (size_t)kb * BLK * DH;
#pragma unroll
        for (int i = 0; i < 8; i++) {
            int idx = tid + 256 * i;
            int mat = idx >> 9;
            int row = (idx >> 3) & 63;
            int seg = idx & 7;
            const __nv_bfloat16* mb = (mat & 2) ? ((mat & 1) ? g_Vl : g_Vh)
                                                : ((mat & 1) ? g_Kl : g_Kh);
            uint32_t dst = sb + AT_STG0 + mat * 8192 + row * 128 + ((seg ^ (row & 7)) << 4);
            cp16(dst, mb + kvb + row * 64 + seg * 8);
        }
    }
    cp_commit();

    float of[8][4];
#pragma unroll
    for (int i = 0; i < 8; i++)
#pragma unroll
        for (int j = 0; j < 4; j++) of[i][j] = 0.f;

    for (int j = 0; j < MBL; j++) {
        if (j + 1 < MBL) {
            int kb = blk_of(j + 1, nb, rand_idx);
            size_t kvb = base + (size_t)kb * BLK * DH;
            uint32_t stg = sb + AT_STG0 + ((j + 1) & 1) * AT_STGSZ;
#pragma unroll
            for (int i = 0; i < 8; i++) {
                int idx = tid + 256 * i;
                int mat = idx >> 9;
                int row = (idx >> 3) & 63;
                int seg = idx & 7;
                const __nv_bfloat16* mb = (mat & 2) ? ((mat & 1) ? g_Vl : g_Vh)
                                                    : ((mat & 1) ? g_Kl : g_Kh);
                uint32_t dst = stg + mat * 8192 + row * 128 + ((seg ^ (row & 7)) << 4);
                cp16(dst, mb + kvb + row * 64 + seg * 8);
            }
            cp_commit();
            cp_wait<1>();
        } else {
            cp_wait<0>();
        }
        __syncthreads();

        const uint32_t stg = sb + AT_STG0 + (j & 1) * AT_STGSZ;

        float sf[4][4];
#pragma unroll
        for (int nf = 0; nf < 4; nf++)
#pragma unroll
            for (int r = 0; r < 4; r++) sf[nf][r] = 0.f;

#pragma unroll
        for (int ks = 0; ks < 4; ks++) {
            const int arow = 16 * wm + r8 + ((tile & 1) << 3);
            const int aseg = ks * 2 + ((tile >> 1) & 1);
            const uint32_t aoff = (uint32_t)(arow * 128 + ((aseg ^ (arow & 7)) << 4));
            uint32_t qh[4], ql[4];
            ldm_x4(qh, sb + AT_QH + aoff);
            ldm_x4(ql, sb + AT_QL + aoff);

            uint32_t kh[2][4], kl[2][4];
#pragma unroll
            for (int p = 0; p < 2; p++) {
                const int brow = 32 * wn + 16 * p + r8 + ((tile >> 1) << 3);
                const int bseg = ks * 2 + (tile & 1);
                const uint32_t boff = (uint32_t)(brow * 128 + ((bseg ^ (brow & 7)) << 4));
                ldm_x4(kh[p], stg + AT_KH + boff);
                ldm_x4(kl[p], stg + AT_KL + boff);
            }
#pragma unroll
            for (int nf = 0; nf < 4; nf++)
                mma_bf16(sf[nf], qh, &kh[nf >> 1][(nf & 1) * 2]);
#pragma unroll
            for (int nf = 0; nf < 4; nf++)
                mma_bf16(sf[nf], qh, &kl[nf >> 1][(nf & 1) * 2]);
#pragma unroll
            for (int nf = 0; nf < 4; nf++)
                mma_bf16(sf[nf], ql, &kh[nf >> 1][(nf & 1) * 2]);
        }

        float rmax0 = sf[0][0], rmax1 = sf[0][2];
#pragma unroll
        for (int nf = 0; nf < 4; nf++) {
            rmax0 = fmaxf(rmax0, fmaxf(sf[nf][0], sf[nf][1]));
            rmax1 = fmaxf(rmax1, fmaxf(sf[nf][2], sf[nf][3]));
        }
        rmax0 = fmaxf(rmax0, __shfl_xor_sync(0xffffffffu, rmax0, 1));
        rmax0 = fmaxf(rmax0, __shfl_xor_sync(0xffffffffu, rmax0, 2));
        rmax1 = fmaxf(rmax1, __shfl_xor_sync(0xffffffffu, rmax1, 1));
        rmax1 = fmaxf(rmax1, __shfl_xor_sync(0xffffffffu, rmax1, 2));
        if ((lane & 3) == 0) {
            pmax[wn * 64 + 16 * wm + qrow]     = rmax0;
            pmax[wn * 64 + 16 * wm + qrow + 8] = rmax1;
        }
        __syncthreads();

        if (tid < 64) {
            float mo = m_s[tid];
            float mn = fmaxf(mo, fmaxf(pmax[tid], pmax[64 + tid]));
            float al = exp2f((mo - mn) * CC);
            m_s[tid] = mn;
            alpha_s[tid] = al;
            l_s[tid] *= al;
        }
        __syncthreads();

        const int r0 = 16 * wm + qrow;
        const float mn0 = m_s[r0], mn1 = m_s[r0 + 8];
        const float al0 = alpha_s[r0], al1 = alpha_s[r0 + 8];

        float rsum0 = 0.f, rsum1 = 0.f;
        uint32_t pah[2][4], pal[2][4];
#pragma unroll
        for (int t = 0; t < 2; t++) {
#pragma unroll
            for (int hl = 0; hl < 2; hl++) {
                int nf = 2 * t + hl;
                float p0 = exp2f((sf[nf][0] - mn0) * CC);
                float p1 = exp2f((sf[nf][1] - mn0) * CC);
                float p2 = exp2f((sf[nf][2] - mn1) * CC);
                float p3 = exp2f((sf[nf][3] - mn1) * CC);
                rsum0 += p0 + p1;
                rsum1 += p2 + p3;
                uint32_t h01 = pack_bf2(p0, p1);
                uint32_t h23 = pack_bf2(p2, p3);
                __nv_bfloat162 hv01 = *(__nv_bfloat162*)&h01;
                __nv_bfloat162 hv23 = *(__nv_bfloat162*)&h23;
                uint32_t l01 = pack_bf2(p0 - __bfloat162float(hv01.x),
                                        p1 - __bfloat162float(hv01.y));
                uint32_t l23 = pack_bf2(p2 - __bfloat162float(hv23.x),
                                        p3 - __bfloat162float(hv23.y));
                pah[t][2 * hl + 0] = h01;
                pah[t][2 * hl + 1] = h23;
                pal[t][2 * hl + 0] = l01;
                pal[t][2 * hl + 1] = l23;
            }
        }
        rsum0 += __shfl_xor_sync(0xffffffffu, rsum0, 1);
        rsum0 += __shfl_xor_sync(0xffffffffu, rsum0, 2);
        rsum1 += __shfl_xor_sync(0xffffffffu, rsum1, 1);
        rsum1 += __shfl_xor_sync(0xffffffffu, rsum1, 2);
        if ((lane & 3) == 0) {
            psum[wn * 64 + r0]     = rsum0;
            psum[wn * 64 + r0 + 8] = rsum1;
        }
#pragma unroll
        for (int nf = 0; nf < 8; nf++) {
            of[nf][0] *= al0; of[nf][1] *= al0;
            of[nf][2] *= al1; of[nf][3] *= al1;
        }

#pragma unroll
        for (int t = 0; t < 2; t++) {
            const int sel = lane >> 3;
            const int vkey = 32 * wn + 16 * t + (lane & 7) + ((sel & 1) << 3);
#pragma unroll
            for (int g = 0; g < 4; g++) {
                const int vseg = 2 * g + (sel >> 1);
                const uint32_t voff = (uint32_t)(vkey * 128 + ((vseg ^ (vkey & 7)) << 4));
                uint32_t vh[4], vl[4];
                ldm_x4t(vh, stg + AT_VH + voff);
                ldm_x4t(vl, stg + AT_VL + voff);
                mma_bf16(of[2 * g + 0], pah[t], &vh[0]);
                mma_bf16(of[2 * g + 1], pah[t], &vh[2]);
                mma_bf16(of[2 * g + 0], pal[t], &vh[0]);
                mma_bf16(of[2 * g + 1], pal[t], &vh[2]);
                mma_bf16(of[2 * g + 0], pah[t], &vl[0]);
                mma_bf16(of[2 * g + 1], pah[t], &vl[2]);
            }
        }
        __syncthreads();
        if (tid < 64) l_s[tid] += psum[tid] + psum[64 + tid];
    }
    __syncthreads();

    // ---- final: reduce partials, divide by l, store bf16 hi/lo AO ----
    float* Os = (float*)(smb + AT_STG0);    // [64][68]
    const int r0 = 16 * wm + qrow;
    if (wn == 1) {
#pragma unroll
        for (int nf = 0; nf < 8; nf++) {
            int d = nf * 8 + qc;
            *(float2*)&Os[r0 * 68 + d]       = make_float2(of[nf][0], of[nf][1]);
            *(float2*)&Os[(r0 + 8) * 68 + d] = make_float2(of[nf][2], of[nf][3]);
        }
    }
    __syncthreads();
    if (wn == 0) {
        const int b = bh >> 3, h = bh & 7;
        const float inv0 = 1.f / l_s[r0];
        const float inv1 = 1.f / l_s[r0 + 8];
        __nv_bfloat16* AOh = g_Inh + 3 * IN_STRIDE;
        __nv_bfloat16* AOl = g_Inl + 3 * IN_STRIDE;
#pragma unroll
        for (int nf = 0; nf < 8; nf++) {
            int d = nf * 8 + qc;
            float2 t0 = *(float2*)&Os[r0 * 68 + d];
            float2 t1 = *(float2*)&Os[(r0 + 8) * 68 + d];
            float v00 = (of[nf][0] + t0.x) * inv0;
            float v01 = (of[nf][1] + t0.y) * inv0;
            float v10 = (of[nf][2] + t1.x) * inv1;
            float v11 = (of[nf][3] + t1.y) * inv1;
            size_t a0 = (size_t)(b * SEQ + nb * BLK + r0) * EMB + h * DH + d;
            size_t a1 = (size_t)(b * SEQ + nb * BLK + r0 + 8) * EMB + h * DH + d;
            __nv_bfloat16 h00 = __float2bfloat16(v00), h01 = __float2bfloat16(v01);
            __nv_bfloat16 h10 = __float2bfloat16(v10), h11 = __float2bfloat16(v11);
            *(__nv_bfloat162*)&AOh[a0] = __halves2bfloat162(h00, h01);
            *(__nv_bfloat162*)&AOh[a1] = __halves2bfloat162(h10, h11);
            *(__nv_bfloat162*)&AOl[a0] = __halves2bfloat162(
                __float2bfloat16(v00 - __bfloat162float(h00)),
                __float2bfloat16(v01 - __bfloat162float(h01)));
            *(__nv_bfloat162*)&AOl[a1] = __halves2bfloat162(
                __float2bfloat16(v10 - __bfloat162float(h10)),
                __float2bfloat16(v11 - __bfloat162float(h11)));
        }
    }
}

// ============================================================
extern "C" void kernel_launch(void* const* d_in, const int* in_sizes, int n_in,
                              void* d_out, int out_size)
{
    const float* query   = (const float*)d_in[0];
    const float* key_inp = (const float*)d_in[1];
    const float* value   = (const float*)d_in[2];
    const float* q_w     = (const float*)d_in[3];
    const float* k_w     = (const float*)d_in[4];
    const float* v_w     = (const float*)d_in[5];
    const float* q_b     = (const float*)d_in[6];
    const float* k_b     = (const float*)d_in[7];
    const float* v_b     = (const float*)d_in[8];
    const float* out_w   = (const float*)d_in[9];
    const float* out_b   = (const float*)d_in[10];
    const int*   rand_idx= (const int*)d_in[11];
    float* out = (float*)d_out;

    static bool attr_set = false;
    if (!attr_set) {
        cudaFuncSetAttribute(attn_mma,
                             cudaFuncAttributeMaxDynamicSharedMemorySize, AT_SMEM);
        cudaFuncSetAttribute(gemm_mma,
                             cudaFuncAttributeMaxDynamicSharedMemorySize, GS_SMEM);
        attr_set = true;
    }

    dim3 gConvW(512, 4);
    conv_weights<<<gConvW, 256>>>(q_w, k_w, v_w, out_w);
    dim3 gConvI(2048, 3);
    conv_inputs<<<gConvI, 256>>>(query, key_inp, value);

    dim3 gQKV(128, 12);
    gemm_mma<<<gQKV, 256, GS_SMEM>>>(q_b, k_b, v_b, out_b, out, 0);

    dim3 gAttn(NBLK, BATCH * NH);
    attn_mma<<<gAttn, 256, AT_SMEM>>>(rand_idx);

    dim3 gOut(128, 4);
    gemm_mma<<<gOut, 256, GS_SMEM>>>(q_b, k_b, v_b, out_b, out, 3);
}

// round 9
// speedup vs baseline: 5.0478x; 1.0515x over previous
#include <cuda_runtime.h>
#include <cuda_bf16.h>
#include <math.h>
#include <cstdint>

#define SEQ   8192
#define BATCH 2
#define EMB   512
#define NH    8
#define DH    64
#define NBLK  128      // SEQ / 64
#define BLK   64
#define MBL   8        // gathered blocks per query block
#define NGLOB 2
#define NWIN  3

#define IN_STRIDE ((size_t)16384 * 512)

// ---- device-global scratch (allocation-free) ----
// A-side activations, bf16 hi/lo: slots 0=q_in 1=k_in 2=v_in 3=attn_out
__device__ __nv_bfloat16 g_Inh[4 * IN_STRIDE];
__device__ __nv_bfloat16 g_Inl[4 * IN_STRIDE];
// Q/K/V (post-projection) bf16 hi/lo, [b][h][s][d]
__device__ __nv_bfloat16 g_Qh[(size_t)BATCH * NH * SEQ * DH];
__device__ __nv_bfloat16 g_Ql[(size_t)BATCH * NH * SEQ * DH];
__device__ __nv_bfloat16 g_Kh[(size_t)BATCH * NH * SEQ * DH];
__device__ __nv_bfloat16 g_Kl[(size_t)BATCH * NH * SEQ * DH];
__device__ __nv_bfloat16 g_Vh[(size_t)BATCH * NH * SEQ * DH];
__device__ __nv_bfloat16 g_Vl[(size_t)BATCH * NH * SEQ * DH];
// bf16 hi/lo split weights: [mat][n][k], mat: 0=q 1=k 2=v 3=out
__device__ __nv_bfloat16 g_Whi[4u * 512u * 512u];
__device__ __nv_bfloat16 g_Wlo[4u * 512u * 512u];

// ============================================================
// helpers (baseline PTX only)
// ============================================================
__device__ __forceinline__ uint32_t smem_u32(const void* p) {
    uint32_t a;
    asm("{ .reg .u64 t; cvta.to.shared.u64 t, %1; cvt.u32.u64 %0, t; }"
        : "=r"(a) : "l"(p));
    return a;
}
__device__ __forceinline__ void ldm_x4(uint32_t* r, uint32_t addr) {
    asm volatile("ldmatrix.sync.aligned.m8n8.x4.shared.b16 {%0,%1,%2,%3}, [%4];"
                 : "=r"(r[0]), "=r"(r[1]), "=r"(r[2]), "=r"(r[3]) : "r"(addr));
}
__device__ __forceinline__ void ldm_x4t(uint32_t* r, uint32_t addr) {
    asm volatile("ldmatrix.sync.aligned.m8n8.x4.trans.shared.b16 {%0,%1,%2,%3}, [%4];"
                 : "=r"(r[0]), "=r"(r[1]), "=r"(r[2]), "=r"(r[3]) : "r"(addr));
}
__device__ __forceinline__ void mma_bf16(float* d, const uint32_t* a, const uint32_t* b) {
    asm volatile(
        "mma.sync.aligned.m16n8k16.row.col.f32.bf16.bf16.f32 "
        "{%0,%1,%2,%3}, {%4,%5,%6,%7}, {%8,%9}, {%0,%1,%2,%3};"
        : "+f"(d[0]), "+f"(d[1]), "+f"(d[2]), "+f"(d[3])
        : "r"(a[0]), "r"(a[1]), "r"(a[2]), "r"(a[3]), "r"(b[0]), "r"(b[1]));
}
__device__ __forceinline__ void cp16(uint32_t dst, const void* src) {
    asm volatile("cp.async.cg.shared.global [%0], [%1], 16;" :: "r"(dst), "l"(src) : "memory");
}
__device__ __forceinline__ void cp_commit() {
    asm volatile("cp.async.commit_group;" ::: "memory");
}
template<int N> __device__ __forceinline__ void cp_wait() {
    asm volatile("cp.async.wait_group %0;" :: "n"(N) : "memory");
}
__device__ __forceinline__ uint32_t pack_bf2(float x, float y) {
    __nv_bfloat162 v = __halves2bfloat162(__float2bfloat16(x), __float2bfloat16(y));
    return *(uint32_t*)&v;
}

// ============================================================
// Fused conversion: weights (fp32->hi/lo [mat][n][k]) + inputs.
// blocks [0,2048): weights; [2048, 8192): inputs.
// ============================================================
__global__ void conv_all(const float* __restrict__ qw, const float* __restrict__ kw,
                         const float* __restrict__ vw, const float* __restrict__ ow,
                         const float* __restrict__ qi, const float* __restrict__ ki,
                         const float* __restrict__ vi)
{
    const int bx = blockIdx.x;
    if (bx < 2048) {
        const int mat = bx >> 9;
        const int n   = bx & 511;
        const float* src = (mat == 0) ? qw : (mat == 1) ? kw : (mat == 2) ? vw : ow;
        for (int k = threadIdx.x; k < 512; k += 256) {
            float v;
            if (mat < 3) v = src[((size_t)(n >> 6) * 512 + k) * 64 + (n & 63)];
            else         v = src[(size_t)n * 512 + k];
            __nv_bfloat16 h = __float2bfloat16(v);
            __nv_bfloat16 l = __float2bfloat16(v - __bfloat162float(h));
            size_t o = (size_t)mat * 262144 + (size_t)n * 512 + k;
            g_Whi[o] = h;
            g_Wlo[o] = l;
        }
    } else {
        const int bi  = bx - 2048;
        const int mat = bi >> 11;
        const int blk = bi & 2047;
        const float* src = (mat == 0) ? qi : (mat == 1) ? ki : vi;
        __nv_bfloat16* dh = g_Inh + (size_t)mat * IN_STRIDE;
        __nv_bfloat16* dl = g_Inl + (size_t)mat * IN_STRIDE;
#pragma unroll
        for (int i = 0; i < 4; i++) {
            size_t o4 = (size_t)blk * 1024 + i * 256 + threadIdx.x;
            float4 x = *(const float4*)&src[o4 * 4];
            __nv_bfloat16 h0 = __float2bfloat16(x.x);
            __nv_bfloat16 h1 = __float2bfloat16(x.y);
            __nv_bfloat16 h2 = __float2bfloat16(x.z);
            __nv_bfloat16 h3 = __float2bfloat16(x.w);
            __nv_bfloat16 l0 = __float2bfloat16(x.x - __bfloat162float(h0));
            __nv_bfloat16 l1 = __float2bfloat16(x.y - __bfloat162float(h1));
            __nv_bfloat16 l2 = __float2bfloat16(x.z - __bfloat162float(h2));
            __nv_bfloat16 l3 = __float2bfloat16(x.w - __bfloat162float(h3));
            *(__nv_bfloat162*)&dh[o4 * 4 + 0] = __halves2bfloat162(h0, h1);
            *(__nv_bfloat162*)&dh[o4 * 4 + 2] = __halves2bfloat162(h2, h3);
            *(__nv_bfloat162*)&dl[o4 * 4 + 0] = __halves2bfloat162(l0, l1);
            *(__nv_bfloat162*)&dl[o4 * 4 + 2] = __halves2bfloat162(l2, l3);
        }
    }
}

// ============================================================
// HMMA GEMM, bf16 hi/lo 3-term, 3-stage cp.async pipeline (R6).
// ============================================================
#define GS_STAGE 32768
#define GS_SMEM  (3 * GS_STAGE)

__global__ __launch_bounds__(256, 2)
void gemm_mma(const float* __restrict__ qb, const float* __restrict__ kb,
              const float* __restrict__ vb, const float* __restrict__ ob,
              float* __restrict__ Cout, int mode_base)
{
    extern __shared__ char gsm[];
    const uint32_t sb = smem_u32(gsm);
    const int tid  = threadIdx.x;
    const int wid  = tid >> 5;
    const int lane = tid & 31;
    const int wm   = wid >> 2;
    const int wn   = wid & 3;
    const int m0   = blockIdx.x * 128;
    const int mode = mode_base + (blockIdx.y >> 2);
    const int n0   = (blockIdx.y & 3) * 128;

    const __nv_bfloat16* __restrict__ Ah = g_Inh + (size_t)mode * IN_STRIDE;
    const __nv_bfloat16* __restrict__ Al = g_Inl + (size_t)mode * IN_STRIDE;
    const __nv_bfloat16* __restrict__ Bh = g_Whi + (size_t)mode * 262144;
    const __nv_bfloat16* __restrict__ Bl = g_Wlo + (size_t)mode * 262144;
    const float* __restrict__ bias = (mode == 0) ? qb : (mode == 1) ? kb
                                   : (mode == 2) ? vb : ob;

#define GPREFETCH(K0, ST)                                                        \
    {                                                                            \
        uint32_t d0 = sb + (ST) * GS_STAGE;                                      \
        _Pragma("unroll")                                                        \
        for (int i = 0; i < 8; i++) {                                            \
            int idx = tid + 256 * i;                                             \
            int mt  = idx >> 9;                                                  \
            int row = (idx >> 2) & 127;                                          \
            int seg = idx & 3;                                                   \
            const __nv_bfloat16* src =                                           \
                (mt == 0) ? Ah + (size_t)(m0 + row) * 512 + (K0) + seg * 8 :     \
                (mt == 1) ? Al + (size_t)(m0 + row) * 512 + (K0) + seg * 8 :     \
                (mt == 2) ? Bh + (size_t)(n0 + row) * 512 + (K0) + seg * 8 :     \
                            Bl + (size_t)(n0 + row) * 512 + (K0) + seg * 8;      \
            cp16(d0 + mt * 8192 + row * 64 + ((seg ^ ((row >> 1) & 3)) << 4),    \
                 src);                                                           \
        }                                                                        \
    }

    GPREFETCH(0, 0);  cp_commit();
    GPREFETCH(32, 1); cp_commit();

    float acc[4][4][4];
#pragma unroll
    for (int i = 0; i < 4; i++)
#pragma unroll
        for (int j = 0; j < 4; j++)
#pragma unroll
            for (int r = 0; r < 4; r++) acc[i][j][r] = 0.f;

    const int tile = lane >> 3;
    const int r8   = lane & 7;

    for (int it = 0; it < 16; it++) {
        if (it < 15) cp_wait<1>(); else cp_wait<0>();
        __syncthreads();
        if (it + 2 < 16) {
            int st = (it + 2) % 3;
            GPREFETCH((it + 2) * 32, st);
            cp_commit();
        }
        const uint32_t stg  = sb + (it % 3) * GS_STAGE;
        const uint32_t aAhi = stg;
        const uint32_t aAlo = stg + 8192;
        const uint32_t aBhi = stg + 16384;
        const uint32_t aBlo = stg + 24576;

#pragma unroll
        for (int ks = 0; ks < 2; ks++) {
            const int k16 = ks * 16;
            const int arow_off = r8 + ((tile & 1) << 3);
            const int aseg = (k16 + ((tile >= 2) ? 8 : 0)) >> 3;
            const int brow_off = r8 + ((tile >> 1) << 3);
            const int bseg = (k16 + ((tile & 1) ? 8 : 0)) >> 3;

            uint32_t ah[4][4], bhf[2][4];
#pragma unroll
            for (int mi = 0; mi < 4; mi++) {
                int row = wm * 64 + mi * 16 + arow_off;
                ldm_x4(ah[mi], aAhi + (uint32_t)(row * 64 + ((aseg ^ ((row >> 1) & 3)) << 4)));
            }
#pragma unroll
            for (int p = 0; p < 2; p++) {
                int row = wn * 32 + p * 16 + brow_off;
                ldm_x4(bhf[p], aBhi + (uint32_t)(row * 64 + ((bseg ^ ((row >> 1) & 3)) << 4)));
            }
#pragma unroll
            for (int mi = 0; mi < 4; mi++)
#pragma unroll
                for (int ni = 0; ni < 4; ni++)
                    mma_bf16(acc[mi][ni], ah[mi], &bhf[ni >> 1][(ni & 1) * 2]);
            {
                uint32_t blf[2][4];
#pragma unroll
                for (int p = 0; p < 2; p++) {
                    int row = wn * 32 + p * 16 + brow_off;
                    ldm_x4(blf[p], aBlo + (uint32_t)(row * 64 + ((bseg ^ ((row >> 1) & 3)) << 4)));
                }
#pragma unroll
                for (int mi = 0; mi < 4; mi++)
#pragma unroll
                    for (int ni = 0; ni < 4; ni++)
                        mma_bf16(acc[mi][ni], ah[mi], &blf[ni >> 1][(ni & 1) * 2]);
            }
            {
                uint32_t al[4][4];
#pragma unroll
                for (int mi = 0; mi < 4; mi++) {
                    int row = wm * 64 + mi * 16 + arow_off;
                    ldm_x4(al[mi], aAlo + (uint32_t)(row * 64 + ((aseg ^ ((row >> 1) & 3)) << 4)));
                }
#pragma unroll
                for (int mi = 0; mi < 4; mi++)
#pragma unroll
                    for (int ni = 0; ni < 4; ni++)
                        mma_bf16(acc[mi][ni], al[mi], &bhf[ni >> 1][(ni & 1) * 2]);
            }
        }
        __syncthreads();
    }

    const int mrb = m0 + wm * 64;
    const int ncb = n0 + wn * 32;
#pragma unroll
    for (int mi = 0; mi < 4; mi++) {
#pragma unroll
        for (int ni = 0; ni < 4; ni++) {
            int n = ncb + ni * 8 + (lane & 3) * 2;
            float2 bv = *(const float2*)&bias[n];
#pragma unroll
            for (int hf = 0; hf < 2; hf++) {
                int m = mrb + mi * 16 + (lane >> 2) + hf * 8;
                float c0 = acc[mi][ni][hf * 2 + 0] + bv.x;
                float c1 = acc[mi][ni][hf * 2 + 1] + bv.y;
                if (mode < 3) {
                    int bb = m & 1, s = m >> 1;
                    int hh = n >> 6, d = n & 63;
                    size_t addr = (((size_t)bb * NH + hh) * SEQ + s) * DH + d;
                    __nv_bfloat16 h0 = __float2bfloat16(c0);
                    __nv_bfloat16 h1 = __float2bfloat16(c1);
                    __nv_bfloat16 e0 = __float2bfloat16(c0 - __bfloat162float(h0));
                    __nv_bfloat16 e1 = __float2bfloat16(c1 - __bfloat162float(h1));
                    __nv_bfloat16* Ch = (mode == 0) ? g_Qh : (mode == 1) ? g_Kh : g_Vh;
                    __nv_bfloat16* Cl = (mode == 0) ? g_Ql : (mode == 1) ? g_Kl : g_Vl;
                    *(__nv_bfloat162*)&Ch[addr] = __halves2bfloat162(h0, h1);
                    *(__nv_bfloat162*)&Cl[addr] = __halves2bfloat162(e0, e1);
                } else {
                    int bb = m >> 13, s = m & (SEQ - 1);
                    *(float2*)&Cout[(size_t)(s * BATCH + bb) * EMB + n] = make_float2(c0, c1);
                }
            }
        }
    }
#undef GPREFETCH
}

// ============================================================
// Attention v3 (fixed): 128 threads, 4 warps; warp = 16 q-rows x ALL 64 keys.
// Softmax stats fully warp-local. Q frags hoisted.
// Smem 48KB: K double-buffered (2x16KB), V single (16KB, doubles as Q stage).
// FIX vs R7: K(j+2) staged into the buffer iteration j used
// ((j&1)?K1:K0), NOT the opposite one (which clobbered in-flight K(j+1)).
// ============================================================
#define AT_K0 0
#define AT_K1 16384
#define AT_V  32768

__device__ __forceinline__ int blk_of(int j, int nb, const int* __restrict__ ri) {
    if (j < NGLOB) return j;
    if (j < NGLOB + NWIN) return (nb + j - 3 + NBLK) & (NBLK - 1);
    return ri[nb * 3 + (j - 5)];
}

__global__ __launch_bounds__(128, 3)
void attn_mma(const int* __restrict__ rand_idx)
{
    __shared__ char smb[49152];
    const uint32_t sb = smem_u32(smb);

    const int nb  = blockIdx.x;
    const int bh  = blockIdx.y;
    const int tid = threadIdx.x;
    const int w    = tid >> 5;
    const int lane = tid & 31;
    const int tile = lane >> 3;
    const int r8   = lane & 7;
    const int sel  = lane >> 3;
    const int qrow = lane >> 2;          // 0..7
    const int qc   = (lane & 3) * 2;
    const size_t base = (size_t)bh * SEQ * DH;
    const float CC = 0.18033688011112042f;   // (1/8) * log2(e)

#define STAGE_HL(DST, SRCH, SRCL, ROWBASE)                                       \
    {                                                                            \
        _Pragma("unroll")                                                        \
        for (int i = 0; i < 8; i++) {                                            \
            int idx = tid + 128 * i;                                             \
            int mh  = idx >> 9;                                                  \
            int row = (idx >> 3) & 63;                                           \
            int seg = idx & 7;                                                   \
            const __nv_bfloat16* src = (mh ? (SRCL) : (SRCH)) + (ROWBASE)        \
                                       + (size_t)row * 64 + seg * 8;             \
            cp16((DST) + mh * 8192 + row * 128 + ((seg ^ (row & 7)) << 4), src); \
        }                                                                        \
    }

    // ---- preload: Q (into V region) + K(0) ----
    STAGE_HL(sb + AT_V,  g_Qh, g_Ql, base + (size_t)nb * BLK * DH);
    STAGE_HL(sb + AT_K0, g_Kh, g_Kl, base + (size_t)blk_of(0, nb, rand_idx) * BLK * DH);
    cp_commit();
    cp_wait<0>();
    __syncthreads();

    // ---- hoist Q fragments ----
    uint32_t qh[4][4], ql[4][4];
#pragma unroll
    for (int ks = 0; ks < 4; ks++) {
        const int arow = 16 * w + r8 + ((tile & 1) << 3);
        const int aseg = ks * 2 + ((tile >> 1) & 1);
        const uint32_t aoff = (uint32_t)(arow * 128 + ((aseg ^ (arow & 7)) << 4));
        ldm_x4(qh[ks], sb + AT_V + aoff);
        ldm_x4(ql[ks], sb + AT_V + 8192 + aoff);
    }
    __syncthreads();   // Q region free -> V can load

    // issue V(0), K(1)
    STAGE_HL(sb + AT_V,  g_Vh, g_Vl, base + (size_t)blk_of(0, nb, rand_idx) * BLK * DH);
    cp_commit();
    STAGE_HL(sb + AT_K1, g_Kh, g_Kl, base + (size_t)blk_of(1, nb, rand_idx) * BLK * DH);
    cp_commit();

    float of[8][4];
#pragma unroll
    for (int i = 0; i < 8; i++)
#pragma unroll
        for (int jj = 0; jj < 4; jj++) of[i][jj] = 0.f;
    float mst0 = -1e30f, mst1 = -1e30f, lst0 = 0.f, lst1 = 0.f;

    for (int j = 0; j < MBL; j++) {
        const uint32_t kbuf = sb + ((j & 1) ? AT_K1 : AT_K0);

        // ---- QK^T: 16 rows x 64 keys ----
        float sf[8][4];
#pragma unroll
        for (int nf = 0; nf < 8; nf++)
#pragma unroll
            for (int r = 0; r < 4; r++) sf[nf][r] = 0.f;

#pragma unroll
        for (int ks = 0; ks < 4; ks++) {
            uint32_t kh[4][4], kl[4][4];
#pragma unroll
            for (int p = 0; p < 4; p++) {
                const int brow = 16 * p + r8 + ((tile >> 1) << 3);
                const int bseg = ks * 2 + (tile & 1);
                const uint32_t boff = (uint32_t)(brow * 128 + ((bseg ^ (brow & 7)) << 4));
                ldm_x4(kh[p], kbuf + boff);
                ldm_x4(kl[p], kbuf + 8192 + boff);
            }
#pragma unroll
            for (int nf = 0; nf < 8; nf++)
                mma_bf16(sf[nf], qh[ks], &kh[nf >> 1][(nf & 1) * 2]);
#pragma unroll
            for (int nf = 0; nf < 8; nf++)
                mma_bf16(sf[nf], qh[ks], &kl[nf >> 1][(nf & 1) * 2]);
#pragma unroll
            for (int nf = 0; nf < 8; nf++)
                mma_bf16(sf[nf], ql[ks], &kh[nf >> 1][(nf & 1) * 2]);
        }

        // ---- warp-local online softmax ----
        float rmax0 = sf[0][0], rmax1 = sf[0][2];
#pragma unroll
        for (int nf = 0; nf < 8; nf++) {
            rmax0 = fmaxf(rmax0, fmaxf(sf[nf][0], sf[nf][1]));
            rmax1 = fmaxf(rmax1, fmaxf(sf[nf][2], sf[nf][3]));
        }
        rmax0 = fmaxf(rmax0, __shfl_xor_sync(0xffffffffu, rmax0, 1));
        rmax0 = fmaxf(rmax0, __shfl_xor_sync(0xffffffffu, rmax0, 2));
        rmax1 = fmaxf(rmax1, __shfl_xor_sync(0xffffffffu, rmax1, 1));
        rmax1 = fmaxf(rmax1, __shfl_xor_sync(0xffffffffu, rmax1, 2));
        const float mn0 = fmaxf(mst0, rmax0);
        const float mn1 = fmaxf(mst1, rmax1);
        const float al0 = exp2f((mst0 - mn0) * CC);
        const float al1 = exp2f((mst1 - mn1) * CC);

        float rsum0 = 0.f, rsum1 = 0.f;
        uint32_t pah[4][4], pal[4][4];
#pragma unroll
        for (int t = 0; t < 4; t++) {
#pragma unroll
            for (int hl = 0; hl < 2; hl++) {
                int nf = 2 * t + hl;
                float p0 = exp2f((sf[nf][0] - mn0) * CC);
                float p1 = exp2f((sf[nf][1] - mn0) * CC);
                float p2 = exp2f((sf[nf][2] - mn1) * CC);
                float p3 = exp2f((sf[nf][3] - mn1) * CC);
                rsum0 += p0 + p1;
                rsum1 += p2 + p3;
                uint32_t h01 = pack_bf2(p0, p1);
                uint32_t h23 = pack_bf2(p2, p3);
                __nv_bfloat162 hv01 = *(__nv_bfloat162*)&h01;
                __nv_bfloat162 hv23 = *(__nv_bfloat162*)&h23;
                pah[t][2 * hl + 0] = h01;
                pah[t][2 * hl + 1] = h23;
                pal[t][2 * hl + 0] = pack_bf2(p0 - __bfloat162float(hv01.x),
                                              p1 - __bfloat162float(hv01.y));
                pal[t][2 * hl + 1] = pack_bf2(p2 - __bfloat162float(hv23.x),
                                              p3 - __bfloat162float(hv23.y));
            }
        }
        rsum0 += __shfl_xor_sync(0xffffffffu, rsum0, 1);
        rsum0 += __shfl_xor_sync(0xffffffffu, rsum0, 2);
        rsum1 += __shfl_xor_sync(0xffffffffu, rsum1, 1);
        rsum1 += __shfl_xor_sync(0xffffffffu, rsum1, 2);
        lst0 = lst0 * al0 + rsum0;
        lst1 = lst1 * al1 + rsum1;
        mst0 = mn0;
        mst1 = mn1;
#pragma unroll
        for (int nf = 0; nf < 8; nf++) {
            of[nf][0] *= al0; of[nf][1] *= al0;
            of[nf][2] *= al1; of[nf][3] *= al1;
        }

        // ---- V(j) ready? ----
        if (j < MBL - 1) cp_wait<1>(); else cp_wait<0>();
        __syncthreads();

        // ---- PV: O += P * V (3-term) ----
#pragma unroll
        for (int t = 0; t < 4; t++) {
            const int vkey = 16 * t + (lane & 7) + ((sel & 1) << 3);
#pragma unroll
            for (int g = 0; g < 4; g++) {
                const int vseg = 2 * g + (sel >> 1);
                const uint32_t voff = (uint32_t)(vkey * 128 + ((vseg ^ (vkey & 7)) << 4));
                uint32_t vh[4], vl[4];
                ldm_x4t(vh, sb + AT_V + voff);
                ldm_x4t(vl, sb + AT_V + 8192 + voff);
                mma_bf16(of[2 * g + 0], pah[t], &vh[0]);
                mma_bf16(of[2 * g + 1], pah[t], &vh[2]);
                mma_bf16(of[2 * g + 0], pal[t], &vh[0]);
                mma_bf16(of[2 * g + 1], pal[t], &vh[2]);
                mma_bf16(of[2 * g + 0], pah[t], &vl[0]);
                mma_bf16(of[2 * g + 1], pah[t], &vl[2]);
            }
        }

        if (j < MBL - 1) {
            cp_wait<0>();      // K(j+1) arrived (this thread)
            __syncthreads();   // K visible to all; V buffer free
            // issue V(j+1); K(j+2) goes into the buffer iteration j used
            size_t v_b = base + (size_t)blk_of(j + 1, nb, rand_idx) * BLK * DH;
            STAGE_HL(sb + AT_V, g_Vh, g_Vl, v_b);
            cp_commit();
            if (j < MBL - 2) {
                size_t k_b = base + (size_t)blk_of(j + 2, nb, rand_idx) * BLK * DH;
                STAGE_HL(sb + ((j & 1) ? AT_K1 : AT_K0), g_Kh, g_Kl, k_b);
                cp_commit();
            }
        }
    }

    // ---- epilogue: direct per-warp store of normalized O (bf16 hi/lo) ----
    const int b = bh >> 3, h = bh & 7;
    const int r0 = 16 * w + qrow;
    const float inv0 = 1.f / lst0;
    const float inv1 = 1.f / lst1;
    __nv_bfloat16* AOh = g_Inh + 3 * IN_STRIDE;
    __nv_bfloat16* AOl = g_Inl + 3 * IN_STRIDE;
#pragma unroll
    for (int nf = 0; nf < 8; nf++) {
        int d = nf * 8 + qc;
        float v00 = of[nf][0] * inv0, v01 = of[nf][1] * inv0;
        float v10 = of[nf][2] * inv1, v11 = of[nf][3] * inv1;
        size_t a0 = (size_t)(b * SEQ + nb * BLK + r0) * EMB + h * DH + d;
        size_t a1 = (size_t)(b * SEQ + nb * BLK + r0 + 8) * EMB + h * DH + d;
        __nv_bfloat16 h00 = __float2bfloat16(v00), h01 = __float2bfloat16(v01);
        __nv_bfloat16 h10 = __float2bfloat16(v10), h11 = __float2bfloat16(v11);
        *(__nv_bfloat162*)&AOh[a0] = __halves2bfloat162(h00, h01);
        *(__nv_bfloat162*)&AOh[a1] = __halves2bfloat162(h10, h11);
        *(__nv_bfloat162*)&AOl[a0] = __halves2bfloat162(
            __float2bfloat16(v00 - __bfloat162float(h00)),
            __float2bfloat16(v01 - __bfloat162float(h01)));
        *(__nv_bfloat162*)&AOl[a1] = __halves2bfloat162(
            __float2bfloat16(v10 - __bfloat162float(h10)),
            __float2bfloat16(v11 - __bfloat162float(h11)));
    }
#undef STAGE_HL
}

// ============================================================
extern "C" void kernel_launch(void* const* d_in, const int* in_sizes, int n_in,
                              void* d_out, int out_size)
{
    const float* query   = (const float*)d_in[0];
    const float* key_inp = (const float*)d_in[1];
    const float* value   = (const float*)d_in[2];
    const float* q_w     = (const float*)d_in[3];
    const float* k_w     = (const float*)d_in[4];
    const float* v_w     = (const float*)d_in[5];
    const float* q_b     = (const float*)d_in[6];
    const float* k_b     = (const float*)d_in[7];
    const float* v_b     = (const float*)d_in[8];
    const float* out_w   = (const float*)d_in[9];
    const float* out_b   = (const float*)d_in[10];
    const int*   rand_idx= (const int*)d_in[11];
    float* out = (float*)d_out;

    static bool attr_set = false;
    if (!attr_set) {
        cudaFuncSetAttribute(gemm_mma,
                             cudaFuncAttributeMaxDynamicSharedMemorySize, GS_SMEM);
        attr_set = true;
    }

    conv_all<<<8192, 256>>>(q_w, k_w, v_w, out_w, query, key_inp, value);

    dim3 gQKV(128, 12);
    gemm_mma<<<gQKV, 256, GS_SMEM>>>(q_b, k_b, v_b, out_b, out, 0);

    dim3 gAttn(NBLK, BATCH * NH);
    attn_mma<<<gAttn, 128>>>(rand_idx);

    dim3 gOut(128, 4);
    gemm_mma<<<gOut, 256, GS_SMEM>>>(q_b, k_b, v_b, out_b, out, 3);
}